// round 8
// baseline (speedup 1.0000x reference)
#include <cuda_runtime.h>
#include <cuda_fp16.h>
#include <cstdint>
#include <math.h>
#include <float.h>

#define N_NODES 100000
#define N_EDGES 1600000
#define DIM 128
#define NB 128
#define NEG 0.01f
#define SCAN_BLOCKS 98   // ceil(100000/1024)
#define TILES 782        // ceil(100000/128)

// ---------------- scratch (static device globals; no allocation) ----------------
struct Zeroed {                              // zeroed by one cudaMemsetAsync per call
    int deg[2][N_NODES];
    unsigned long long look[2][SCAN_BLOCKS]; // lookback descriptors: (flag<<62)|value
};
__device__ Zeroed g_z;
__device__ __align__(16) uint4 g_xh[2][(size_t)N_NODES * 16]; // pre-scaled x̂ fp16, row = 16 uint4 = 128 halves
__device__ float  g_dinv[2][N_NODES];
__device__ int    g_offs[2][N_NODES + 1];
__device__ int    g_cursor[2][N_NODES];
__device__ int    g_csr[2][N_EDGES];
// A operand in mma-fragment layout: frag (tile, rb(8), kc(8)) = 256 halves, thread-contiguous
__device__ __align__(16) __half g_Ah[2][(size_t)TILES * 64 * 256];
__device__ __align__(16) __half g_Al[2][(size_t)TILES * 64 * 256];
__device__ __align__(16) __half g_Wt[2][2][128 * 128];   // [branch][hi/lo], [n][k] fp16
__device__ float g_pool[2 * NB * DIM];
__device__ float g_gp[2 * NB * DIM];
__device__ float g_c1[NB * 256];
__device__ float g_c2[NB * 64];

__device__ __forceinline__ float lrelu(float v) { return v >= 0.f ? v : NEG * v; }

__device__ __forceinline__ void atomicMaxFloat(float* addr, float v) {
    if (v >= 0.f) atomicMax((int*)addr, __float_as_int(v));
    else          atomicMin((unsigned int*)addr, __float_as_uint(v));
}

// mma.sync m16n8k16 fp16 in / fp32 accum (sm_80 PTX; legal on compute_103)
#define MMA4(c, a, bb0, bb1) \
    asm volatile("mma.sync.aligned.m16n8k16.row.col.f32.f16.f16.f32 " \
        "{%0,%1,%2,%3}, {%4,%5,%6,%7}, {%8,%9}, {%0,%1,%2,%3};" \
        : "+f"((c)[0]), "+f"((c)[1]), "+f"((c)[2]), "+f"((c)[3]) \
        : "r"((a).x), "r"((a).y), "r"((a).z), "r"((a).w), "r"(bb0), "r"(bb1))

// packed f32x2 accumulate: acc += h2 (converted), via FFMA2 with multiplier 1.0 (known-good on this build)
__device__ __forceinline__ void acc_h2(unsigned long long& acc, unsigned h2bits,
                                       unsigned long long one2) {
    float2 f = __half22float2(*(__half2*)&h2bits);
    unsigned long long t;
    asm("mov.b64 %0, {%1, %2};" : "=l"(t) : "f"(f.x), "f"(f.y));
    asm("fma.rn.f32x2 %0, %1, %2, %0;" : "+l"(acc) : "l"(t), "l"(one2));
}

// ---------------- launch 0: degree count ----------------
__global__ void k_count(const int* __restrict__ col0, const int* __restrict__ col1) {
    int p = blockIdx.y;
    const int* col = p ? col1 : col0;
    int e = blockIdx.x * blockDim.x + threadIdx.x;
    if (e < N_EDGES) atomicAdd(&g_z.deg[p][col[e]], 1);
}

// ---------------- launch 1: scan + dinv + cursor + pool init + x̂ transcode + W split ----------------
__global__ void k_scan(const float* __restrict__ x0, const float* __restrict__ x1,
                       const float* __restrict__ W0, const float* __restrict__ W1) {
    __shared__ int sh[1024];
    __shared__ int sE;
    const int p = blockIdx.y;
    const int b = blockIdx.x;
    const int t = threadIdx.x;
    const int i = b * 1024 + t;
    const int lane = t & 31;

    int v = (i < N_NODES) ? g_z.deg[p][i] : 0;
    if (i < N_NODES) g_dinv[p][i] = rsqrtf((float)(v + 1));   // +1 self loop
    sh[t] = v;
    __syncthreads();
    #pragma unroll
    for (int off = 1; off < 1024; off <<= 1) {
        int x = (t >= off) ? sh[t - off] : 0;
        __syncthreads();
        sh[t] += x;
        __syncthreads();
    }
    const int total = sh[1023];

    if (b > 0 && t == 0)
        *(volatile unsigned long long*)&g_z.look[p][b] = (1ULL << 62) | (unsigned)total;
    if (t < 32) {   // warp 0 resolves exclusive prefix E
        int E = 0;
        if (b > 0) {
            int base = b - 1;
            int accum = 0;
            bool done = false;
            while (!done) {
                int idx = base - lane;
                unsigned long long w = (idx >= 0)
                    ? *(volatile unsigned long long*)&g_z.look[p][idx]
                    : (2ULL << 62);
                int flg = (int)(w >> 62);
                int val = (int)(w & 0xffffffffULL);
                unsigned m2 = __ballot_sync(0xffffffffu, flg == 2);
                unsigned m1 = __ballot_sync(0xffffffffu, flg >= 1);
                if (m2) {
                    int t2 = __ffs(m2) - 1;
                    unsigned below = (t2 == 0) ? 0u : ((1u << t2) - 1u);
                    if ((m1 & below) == below) {
                        int c = (lane <= t2) ? val : 0;
                        #pragma unroll
                        for (int o = 16; o; o >>= 1) c += __shfl_xor_sync(0xffffffffu, c, o);
                        accum += c;
                        done = true;
                    }
                } else if (m1 == 0xffffffffu) {
                    int c = (idx >= 0) ? val : 0;
                    #pragma unroll
                    for (int o = 16; o; o >>= 1) c += __shfl_xor_sync(0xffffffffu, c, o);
                    accum += c;
                    base -= 32;
                }
            }
            E = accum;
        }
        if (lane == 0) {
            *(volatile unsigned long long*)&g_z.look[p][b] = (2ULL << 62) | (unsigned)(E + total);
            sE = E;
        }
    }
    __syncthreads();
    const int E = sE;

    if (i < N_NODES) {
        int ex = E + sh[t] - v;
        g_offs[p][i] = ex;
        g_cursor[p][i] = ex;
    }
    if (b == 0 && t == 0) g_offs[p][N_NODES] = N_EDGES;
    if (b == 0) {
        #pragma unroll
        for (int it = 0; it < 16; it++)
            g_pool[p * NB * DIM + it * 1024 + t] = -FLT_MAX;
    }
    if (b == 1) {   // W hi/lo split -> [n][k] fp16 (coalesced reads, scattered one-time writes)
        const float* Wsrc = p ? W1 : W0;
        #pragma unroll
        for (int it = 0; it < 16; it++) {
            int idx = t + it * 1024;            // 16384
            int k = idx >> 7, n = idx & 127;
            float wv = Wsrc[idx];
            __half hh = __float2half_rn(wv);
            __half hl = __float2half_rn(wv - __half2float(hh));
            g_Wt[p][0][n * 128 + k] = hh;
            g_Wt[p][1][n * 128 + k] = hl;
        }
    }

    // ---- transcode tail: x̂ = dinv[src] * x (fp16), coalesced, 32 nodes/warp ----
    {
        const float4* xs = (const float4*)(p ? x1 : x0);
        const int w = t >> 5;
        const int nb = b * 1024 + w * 32;
        for (int nd = 0; nd < 32; nd++) {
            int i2 = nb + nd;
            if (i2 >= N_NODES) break;
            float s = rsqrtf((float)(g_z.deg[p][i2] + 1));
            float4 xv = xs[(size_t)i2 * 32 + lane];
            __half2 h0 = __floats2half2_rn(s * xv.x, s * xv.y);
            __half2 h1 = __floats2half2_rn(s * xv.z, s * xv.w);
            uint2 o;
            o.x = *(unsigned*)&h0; o.y = *(unsigned*)&h1;
            ((uint2*)g_xh[p])[(size_t)i2 * 32 + lane] = o;
        }
    }
}

// ---------------- launch 2: CSR fill ----------------
__global__ void k_fill(const int* __restrict__ row0, const int* __restrict__ col0,
                       const int* __restrict__ row1, const int* __restrict__ col1) {
    int p = blockIdx.y;
    const int* row = p ? row1 : row0;
    const int* col = p ? col1 : col0;
    int e = blockIdx.x * blockDim.x + threadIdx.x;
    if (e < N_EDGES) {
        int d = col[e];
        int pos = atomicAdd(&g_cursor[p][d], 1);
        g_csr[p][pos] = row[e];
    }
}

// ---------------- launch 3 (CAPTURED): gather, half-warp per edge ----------------
__global__ void k_gather() {
    int p = blockIdx.y;
    const int* csr = g_csr[p];
    int gw = (blockIdx.x * blockDim.x + threadIdx.x) >> 5;
    int lane = threadIdx.x & 31;
    if (gw >= N_NODES) return;
    const int i = gw;
    const int half = lane >> 4, li = lane & 15;
    const uint4* xp = g_xh[p] + li;              // lane's 16B of each row
    const float di = g_dinv[p][i];

    unsigned long long one2;
    asm("mov.b64 %0, {%1, %1};" : "=l"(one2) : "f"(1.0f));
    unsigned long long acc[4] = {0ULL, 0ULL, 0ULL, 0ULL};

    if (half == 0) {                             // self term (once)
        uint4 u = xp[(size_t)i * 16];
        acc_h2(acc[0], u.x, one2); acc_h2(acc[1], u.y, one2);
        acc_h2(acc[2], u.z, one2); acc_h2(acc[3], u.w, one2);
    }

    int j = g_offs[p][i];
    const int s1 = g_offs[p][i + 1];
    for (; j + 4 <= s1; j += 4) {                // 4 edges: 2 per half-warp
        int sa = csr[j + half];
        int sb = csr[j + 2 + half];
        uint4 ua = xp[(size_t)sa * 16];
        uint4 ub = xp[(size_t)sb * 16];
        acc_h2(acc[0], ua.x, one2); acc_h2(acc[1], ua.y, one2);
        acc_h2(acc[2], ua.z, one2); acc_h2(acc[3], ua.w, one2);
        acc_h2(acc[0], ub.x, one2); acc_h2(acc[1], ub.y, one2);
        acc_h2(acc[2], ub.z, one2); acc_h2(acc[3], ub.w, one2);
    }
    if (j + 2 <= s1) {
        int s = csr[j + half];
        uint4 u = xp[(size_t)s * 16];
        acc_h2(acc[0], u.x, one2); acc_h2(acc[1], u.y, one2);
        acc_h2(acc[2], u.z, one2); acc_h2(acc[3], u.w, one2);
        j += 2;
    }
    if (j < s1 && half == 0) {                   // odd remainder: half 0 only
        int s = csr[j];
        uint4 u = xp[(size_t)s * 16];
        acc_h2(acc[0], u.x, one2); acc_h2(acc[1], u.y, one2);
        acc_h2(acc[2], u.z, one2); acc_h2(acc[3], u.w, one2);
    }

    // merge halves + scale by dinv[dst]
    float f[8];
    #pragma unroll
    for (int q = 0; q < 4; q++) {
        unsigned lo, hi;
        asm("mov.b64 {%0, %1}, %2;" : "=r"(lo), "=r"(hi) : "l"(acc[q]));
        f[2 * q]     = __uint_as_float(lo);
        f[2 * q + 1] = __uint_as_float(hi);
    }
    #pragma unroll
    for (int m = 0; m < 8; m++)
        f[m] = (f[m] + __shfl_xor_sync(0xffffffffu, f[m], 16)) * di;

    // hi/lo fp16 split; half 0 stores hi, half 1 stores lo
    __half hh[8];
    float  fl[8];
    #pragma unroll
    for (int m = 0; m < 8; m++) { hh[m] = __float2half_rn(f[m]); fl[m] = f[m] - __half2float(hh[m]); }

    const int tile = i >> 7, rb = (i >> 4) & 7, r16 = i & 15, kc = li >> 1;
    __half* dst = half ? g_Al[p] : g_Ah[p];
    const size_t base = ((((size_t)tile * 8 + rb) * 8 + kc) << 8)
                      + (size_t)((r16 & 7) * 32 + (r16 >> 3) * 2 + (li & 1) * 4);
    #pragma unroll
    for (int m2 = 0; m2 < 4; m2++) {
        __half2 vv = half ? __floats2half2_rn(fl[2 * m2], fl[2 * m2 + 1])
                          : __halves2half2(hh[2 * m2], hh[2 * m2 + 1]);
        *(__half2*)&dst[base + (size_t)m2 * 8] = vv;
    }
}

// ---------------- launch 4: mma.sync split-fp16 GEMM + lrelu + segment_max epilogue ----------------
#define W_STRIDE 68
#define SMEM_GEMM ((2 * 128 * W_STRIDE + 128) * 4)

__global__ void __launch_bounds__(512, 2)
k_gemm_pool(const float* __restrict__ b0, const float* __restrict__ b1,
            const int* __restrict__ batch0, const int* __restrict__ batch1) {
    extern __shared__ uint32_t smem[];
    uint32_t* hiP = smem;                       // [128][W_STRIDE] u32 (k-pairs)
    uint32_t* loP = smem + 128 * W_STRIDE;
    float* s_bias = (float*)(smem + 2 * 128 * W_STRIDE);

    const int p = blockIdx.y, tile = blockIdx.x;
    const float* __restrict__ bias  = p ? b1 : b0;
    const int*   __restrict__ batch = p ? batch1 : batch0;
    const int tid = threadIdx.x, lane = tid & 31, w = tid >> 5;
    const int w_m = w & 7, nh = w >> 3;

    // stage pre-split W -> smem with pad (straight copy)
    {
        const uint32_t* srcH = (const uint32_t*)g_Wt[p][0];
        const uint32_t* srcL = (const uint32_t*)g_Wt[p][1];
        #pragma unroll
        for (int it = 0; it < 16; it++) {
            int idx = tid + it * 512;           // 8192 u32
            int n = idx >> 6, ku = idx & 63;
            hiP[n * W_STRIDE + ku] = srcH[idx];
            loP[n * W_STRIDE + ku] = srcL[idx];
        }
    }
    if (tid < 128) s_bias[tid] = bias[tid];
    __syncthreads();

    float acc[8][4];
    #pragma unroll
    for (int jj = 0; jj < 8; jj++)
        #pragma unroll
        for (int q = 0; q < 4; q++) acc[jj][q] = 0.f;

    const __half* Ah = g_Ah[p];
    const __half* Al = g_Al[p];
    const size_t abase = ((size_t)tile * 8 + w_m) * 8;
    #pragma unroll
    for (int kc = 0; kc < 8; kc++) {
        uint4 ah = *(const uint4*)&Ah[((abase + kc) << 8) + lane * 8];
        uint4 al = *(const uint4*)&Al[((abase + kc) << 8) + lane * 8];
        #pragma unroll
        for (int jj = 0; jj < 8; jj++) {
            int n = (nh * 8 + jj) * 8 + (lane >> 2);
            int ku = kc * 8 + (lane & 3);
            uint32_t b0h = hiP[n * W_STRIDE + ku], b1h = hiP[n * W_STRIDE + ku + 4];
            uint32_t b0l = loP[n * W_STRIDE + ku], b1l = loP[n * W_STRIDE + ku + 4];
            MMA4(acc[jj], ah, b0h, b1h);
            MMA4(acc[jj], ah, b0l, b1l);
            MMA4(acc[jj], al, b0h, b1h);
        }
    }

    // epilogue: segment_max into pool
    const int r_base = tile * 128 + w_m * 16;
    float* pool = &g_pool[p * NB * DIM];
    const bool full = (r_base + 15 < N_NODES);
    const bool any  = (r_base < N_NODES);
    int btA = any ? batch[r_base] : -1;
    int btB = full ? batch[r_base + 15] : -2;

    if (full && btA == btB) {
        #pragma unroll
        for (int jj = 0; jj < 8; jj++) {
            float m0 = fmaxf(acc[jj][0], acc[jj][2]);
            float m1 = fmaxf(acc[jj][1], acc[jj][3]);
            #pragma unroll
            for (int o = 4; o <= 16; o <<= 1) {
                m0 = fmaxf(m0, __shfl_xor_sync(0xffffffffu, m0, o));
                m1 = fmaxf(m1, __shfl_xor_sync(0xffffffffu, m1, o));
            }
            if ((lane >> 2) == 0) {
                int c = (nh * 8 + jj) * 8 + (lane & 3) * 2;
                atomicMaxFloat(&pool[btA * DIM + c],     lrelu(m0 + s_bias[c]));
                atomicMaxFloat(&pool[btA * DIM + c + 1], lrelu(m1 + s_bias[c + 1]));
            }
        }
    } else if (any) {
        int r0 = r_base + (lane >> 2), r1 = r0 + 8;
        int bt0 = (r0 < N_NODES) ? batch[r0] : -1;
        int bt1 = (r1 < N_NODES) ? batch[r1] : -1;
        #pragma unroll
        for (int jj = 0; jj < 8; jj++) {
            int c = (nh * 8 + jj) * 8 + (lane & 3) * 2;
            if (bt0 >= 0) {
                atomicMaxFloat(&pool[bt0 * DIM + c],     lrelu(acc[jj][0] + s_bias[c]));
                atomicMaxFloat(&pool[bt0 * DIM + c + 1], lrelu(acc[jj][1] + s_bias[c + 1]));
            }
            if (bt1 >= 0) {
                atomicMaxFloat(&pool[bt1 * DIM + c],     lrelu(acc[jj][2] + s_bias[c]));
                atomicMaxFloat(&pool[bt1 * DIM + c + 1], lrelu(acc[jj][3] + s_bias[c + 1]));
            }
        }
    }
}

// ---------------- tail MLPs (tiny) ----------------
__global__ void k_fcp(const float* __restrict__ W1, const float* __restrict__ b1,
                      const float* __restrict__ W2, const float* __restrict__ b2) {
    int p = blockIdx.y, r = blockIdx.x, d = threadIdx.x;
    __shared__ float prow[128];
    prow[d] = g_pool[p * NB * DIM + r * 128 + d];
    __syncthreads();
    const float* W = p ? W2 : W1;
    const float* bb = p ? b2 : b1;
    float s = bb[d];
    #pragma unroll 8
    for (int k = 0; k < 128; k++) s += prow[k] * W[k * 128 + d];
    g_gp[p * NB * DIM + r * 128 + d] = lrelu(s);
}

__global__ void k_fc1(const float* __restrict__ W, const float* __restrict__ b) {
    int r = blockIdx.x, d = threadIdx.x;
    __shared__ float in[256];
    in[d] = (d < 128) ? g_gp[r * 128 + d] : g_gp[NB * DIM + r * 128 + (d - 128)];
    __syncthreads();
    float s = b[d];
    #pragma unroll 8
    for (int k = 0; k < 256; k++) s += in[k] * W[k * 256 + d];
    g_c1[r * 256 + d] = lrelu(s);
}

__global__ void k_fc2(const float* __restrict__ W, const float* __restrict__ b) {
    int r = blockIdx.x, d = threadIdx.x;
    __shared__ float in[256];
    for (int k = d; k < 256; k += 64) in[k] = g_c1[r * 256 + k];
    __syncthreads();
    float s = b[d];
    #pragma unroll 8
    for (int k = 0; k < 256; k++) s += in[k] * W[k * 64 + d];
    g_c2[r * 64 + d] = lrelu(s);
}

__global__ void k_out(const float* __restrict__ W, const float* __restrict__ b,
                      float* __restrict__ out) {
    int r = threadIdx.x;
    float s = b[0];
    #pragma unroll
    for (int k = 0; k < 64; k++) s += g_c2[r * 64 + k] * W[k];
    out[r] = 1.f / (1.f + expf(-s));
}

// ---------------- host launcher ----------------
extern "C" void kernel_launch(void* const* d_in, const int* in_sizes, int n_in,
                              void* d_out, int out_size) {
    int ix[2], ie[2], ib[2];
    if (in_sizes[1] == N_NODES * DIM) {
        ix[0] = 0; ix[1] = 1; ie[0] = 2; ie[1] = 3; ib[0] = 4; ib[1] = 5;   // dict order
    } else {
        ix[0] = 0; ie[0] = 1; ib[0] = 2; ix[1] = 3; ie[1] = 4; ib[1] = 5;   // signature order
    }
    const float* x0 = (const float*)d_in[ix[0]];
    const float* x1 = (const float*)d_in[ix[1]];
    const int* row0 = (const int*)d_in[ie[0]];
    const int* col0 = row0 + N_EDGES;
    const int* row1 = (const int*)d_in[ie[1]];
    const int* col1 = row1 + N_EDGES;
    const int* bat0 = (const int*)d_in[ib[0]];
    const int* bat1 = (const int*)d_in[ib[1]];

    const float* convW0 = (const float*)d_in[6];
    const float* convB0 = (const float*)d_in[7];
    const float* convW1 = (const float*)d_in[8];
    const float* convB1 = (const float*)d_in[9];
    const float* fcp1W = (const float*)d_in[10];
    const float* fcp1B = (const float*)d_in[11];
    const float* fcp2W = (const float*)d_in[12];
    const float* fcp2B = (const float*)d_in[13];
    const float* fc1W  = (const float*)d_in[14];
    const float* fc1B  = (const float*)d_in[15];
    const float* fc2W  = (const float*)d_in[16];
    const float* fc2B  = (const float*)d_in[17];
    const float* outW  = (const float*)d_in[18];
    const float* outB  = (const float*)d_in[19];

    static bool attr_done = false;
    if (!attr_done) {
        cudaFuncSetAttribute(k_gemm_pool, cudaFuncAttributeMaxDynamicSharedMemorySize, SMEM_GEMM);
        attr_done = true;
    }

    void* zPtr = nullptr;
    cudaGetSymbolAddress(&zPtr, g_z);
    cudaMemsetAsync(zPtr, 0, sizeof(Zeroed));

    k_count<<<dim3((N_EDGES + 255) / 256, 2), 256>>>(col0, col1);            // launch 0
    k_scan<<<dim3(SCAN_BLOCKS, 2), 1024>>>(x0, x1, convW0, convW1);          // launch 1
    k_fill<<<dim3((N_EDGES + 255) / 256, 2), 256>>>(row0, col0, row1, col1); // launch 2
    k_gather<<<dim3((N_NODES * 32 + 255) / 256, 2), 256>>>();                // launch 3 (captured)
    k_gemm_pool<<<dim3(TILES, 2), 512, SMEM_GEMM>>>(convB0, convB1, bat0, bat1);

    k_fcp<<<dim3(NB, 2), 128>>>(fcp1W, fcp1B, fcp2W, fcp2B);
    k_fc1<<<NB, 256>>>(fc1W, fc1B);
    k_fc2<<<NB, 64>>>(fc2W, fc2B);
    k_out<<<1, 128>>>(outW, outB, (float*)d_out);
}

// round 9
// speedup vs baseline: 1.0681x; 1.0681x over previous
#include <cuda_runtime.h>
#include <cuda_fp16.h>
#include <cstdint>
#include <math.h>
#include <float.h>

#define N_NODES 100000
#define N_EDGES 1600000
#define DIM 128
#define NB 128
#define NEG 0.01f
#define SCAN_BLOCKS 98   // ceil(100000/1024)
#define TILES 782        // ceil(100000/128)

// ---------------- scratch (static device globals; no allocation) ----------------
struct Zeroed {                              // zeroed by one cudaMemsetAsync per call
    int deg[2][N_NODES];
    unsigned long long look[2][SCAN_BLOCKS]; // lookback descriptors: (flag<<62)|value
};
__device__ Zeroed g_z;
__device__ __align__(16) uint2 g_xh[2][(size_t)N_NODES * 32]; // pre-scaled x̂ fp16, 4 halves/lane
__device__ float  g_dinv[2][N_NODES];
__device__ int    g_offs[2][N_NODES + 1];
__device__ int    g_cursor[2][N_NODES];
__device__ __align__(16) int g_csr[2][N_EDGES];
// A operand in mma-fragment layout: frag (tile, rb(8), kc(8)) = 256 halves, thread-contiguous
__device__ __align__(16) __half g_Ah[2][(size_t)TILES * 64 * 256];
__device__ __align__(16) __half g_Al[2][(size_t)TILES * 64 * 256];
__device__ __align__(16) __half g_Wt[2][2][128 * 128];   // [branch][hi/lo], [n][k] fp16
__device__ float g_pool[2 * NB * DIM];
__device__ float g_gp[2 * NB * DIM];
__device__ float g_c1[NB * 256];
__device__ float g_c2[NB * 64];

__device__ __forceinline__ float lrelu(float v) { return v >= 0.f ? v : NEG * v; }

__device__ __forceinline__ void atomicMaxFloat(float* addr, float v) {
    if (v >= 0.f) atomicMax((int*)addr, __float_as_int(v));
    else          atomicMin((unsigned int*)addr, __float_as_uint(v));
}

// mma.sync m16n8k16 fp16 in / fp32 accum (sm_80 PTX; legal on compute_103)
#define MMA4(c, a, bb0, bb1) \
    asm volatile("mma.sync.aligned.m16n8k16.row.col.f32.f16.f16.f32 " \
        "{%0,%1,%2,%3}, {%4,%5,%6,%7}, {%8,%9}, {%0,%1,%2,%3};" \
        : "+f"((c)[0]), "+f"((c)[1]), "+f"((c)[2]), "+f"((c)[3]) \
        : "r"((a).x), "r"((a).y), "r"((a).z), "r"((a).w), "r"(bb0), "r"(bb1))

// ---------------- launch 0: degree count ----------------
__global__ void k_count(const int* __restrict__ col0, const int* __restrict__ col1) {
    int p = blockIdx.y;
    const int* col = p ? col1 : col0;
    int e = blockIdx.x * blockDim.x + threadIdx.x;
    if (e < N_EDGES) atomicAdd(&g_z.deg[p][col[e]], 1);
}

// ---------------- launch 1: scan + dinv + cursor + pool init + x̂ transcode + W split ----------------
__global__ void k_scan(const float* __restrict__ x0, const float* __restrict__ x1,
                       const float* __restrict__ W0, const float* __restrict__ W1) {
    __shared__ int sh[1024];
    __shared__ int sE;
    const int p = blockIdx.y;
    const int b = blockIdx.x;
    const int t = threadIdx.x;
    const int i = b * 1024 + t;
    const int lane = t & 31;

    int v = (i < N_NODES) ? g_z.deg[p][i] : 0;
    if (i < N_NODES) g_dinv[p][i] = rsqrtf((float)(v + 1));   // +1 self loop
    sh[t] = v;
    __syncthreads();
    #pragma unroll
    for (int off = 1; off < 1024; off <<= 1) {
        int x = (t >= off) ? sh[t - off] : 0;
        __syncthreads();
        sh[t] += x;
        __syncthreads();
    }
    const int total = sh[1023];

    if (b > 0 && t == 0)
        *(volatile unsigned long long*)&g_z.look[p][b] = (1ULL << 62) | (unsigned)total;
    if (t < 32) {   // warp 0 resolves exclusive prefix E
        int E = 0;
        if (b > 0) {
            int base = b - 1;
            int accum = 0;
            bool done = false;
            while (!done) {
                int idx = base - lane;
                unsigned long long w = (idx >= 0)
                    ? *(volatile unsigned long long*)&g_z.look[p][idx]
                    : (2ULL << 62);
                int flg = (int)(w >> 62);
                int val = (int)(w & 0xffffffffULL);
                unsigned m2 = __ballot_sync(0xffffffffu, flg == 2);
                unsigned m1 = __ballot_sync(0xffffffffu, flg >= 1);
                if (m2) {
                    int t2 = __ffs(m2) - 1;
                    unsigned below = (t2 == 0) ? 0u : ((1u << t2) - 1u);
                    if ((m1 & below) == below) {
                        int c = (lane <= t2) ? val : 0;
                        #pragma unroll
                        for (int o = 16; o; o >>= 1) c += __shfl_xor_sync(0xffffffffu, c, o);
                        accum += c;
                        done = true;
                    }
                } else if (m1 == 0xffffffffu) {
                    int c = (idx >= 0) ? val : 0;
                    #pragma unroll
                    for (int o = 16; o; o >>= 1) c += __shfl_xor_sync(0xffffffffu, c, o);
                    accum += c;
                    base -= 32;
                }
            }
            E = accum;
        }
        if (lane == 0) {
            *(volatile unsigned long long*)&g_z.look[p][b] = (2ULL << 62) | (unsigned)(E + total);
            sE = E;
        }
    }
    __syncthreads();
    const int E = sE;

    if (i < N_NODES) {
        int ex = E + sh[t] - v;
        g_offs[p][i] = ex;
        g_cursor[p][i] = ex;
    }
    if (b == 0 && t == 0) g_offs[p][N_NODES] = N_EDGES;
    if (b == 0) {
        #pragma unroll
        for (int it = 0; it < 16; it++)
            g_pool[p * NB * DIM + it * 1024 + t] = -FLT_MAX;
    }
    if (b == 1) {   // W hi/lo split -> [n][k] fp16 (coalesced reads, one-time scattered writes)
        const float* Wsrc = p ? W1 : W0;
        #pragma unroll
        for (int it = 0; it < 16; it++) {
            int idx = t + it * 1024;            // 16384
            int k = idx >> 7, n = idx & 127;
            float wv = Wsrc[idx];
            __half hh = __float2half_rn(wv);
            __half hl = __float2half_rn(wv - __half2float(hh));
            g_Wt[p][0][n * 128 + k] = hh;
            g_Wt[p][1][n * 128 + k] = hl;
        }
    }

    // ---- transcode tail: x̂ = dinv[src] * x (fp16), coalesced, 32 nodes/warp ----
    {
        const float4* xs = (const float4*)(p ? x1 : x0);
        const int w = t >> 5;
        const int nb = b * 1024 + w * 32;
        for (int nd = 0; nd < 32; nd++) {
            int i2 = nb + nd;
            if (i2 >= N_NODES) break;
            float s = rsqrtf((float)(g_z.deg[p][i2] + 1));
            float4 xv = xs[(size_t)i2 * 32 + lane];
            __half2 h0 = __floats2half2_rn(s * xv.x, s * xv.y);
            __half2 h1 = __floats2half2_rn(s * xv.z, s * xv.w);
            uint2 o;
            o.x = *(unsigned*)&h0; o.y = *(unsigned*)&h1;
            g_xh[p][(size_t)i2 * 32 + lane] = o;
        }
    }
}

// ---------------- launch 2: CSR fill ----------------
__global__ void k_fill(const int* __restrict__ row0, const int* __restrict__ col0,
                       const int* __restrict__ row1, const int* __restrict__ col1) {
    int p = blockIdx.y;
    const int* row = p ? row1 : row0;
    const int* col = p ? col1 : col0;
    int e = blockIdx.x * blockDim.x + threadIdx.x;
    if (e < N_EDGES) {
        int d = col[e];
        int pos = atomicAdd(&g_cursor[p][d], 1);
        g_csr[p][pos] = row[e];
    }
}

// ---------------- launch 3 (CAPTURED): gather (pre-scaled fp16) -> mma-frag hi/lo (R7 shape + int4 csr) ----------------
__global__ void k_gather() {
    int p = blockIdx.y;
    const uint2* xh  = g_xh[p];
    const int*   csr = g_csr[p];

    int gw = (blockIdx.x * blockDim.x + threadIdx.x) >> 5;
    int lane = threadIdx.x & 31;
    if (gw >= N_NODES) return;
    const int i = gw;
    const float di = g_dinv[p][i];

    float4 acc;
    {
        uint2 u = xh[(size_t)i * 32 + lane];   // self term
        float2 fa = __half22float2(*(__half2*)&u.x), fb = __half22float2(*(__half2*)&u.y);
        acc.x = fa.x; acc.y = fa.y; acc.z = fb.x; acc.w = fb.y;
    }

    int j = g_offs[p][i];
    const int s1 = g_offs[p][i + 1];
    // peel to 16B alignment of csr index
    for (; j < s1 && (j & 3); j++) {
        int s = csr[j];
        uint2 u = xh[(size_t)s * 32 + lane];
        float2 f0 = __half22float2(*(__half2*)&u.x), f1 = __half22float2(*(__half2*)&u.y);
        acc.x += f0.x; acc.y += f0.y; acc.z += f1.x; acc.w += f1.y;
    }
    for (; j + 4 <= s1; j += 4) {
        int4 c4 = *(const int4*)&csr[j];       // one LDG.128 for 4 indices
        uint2 ua = xh[(size_t)c4.x * 32 + lane];
        uint2 ub = xh[(size_t)c4.y * 32 + lane];
        uint2 uc = xh[(size_t)c4.z * 32 + lane];
        uint2 ud = xh[(size_t)c4.w * 32 + lane];
        float2 a0 = __half22float2(*(__half2*)&ua.x), a1 = __half22float2(*(__half2*)&ua.y);
        float2 b0 = __half22float2(*(__half2*)&ub.x), b1 = __half22float2(*(__half2*)&ub.y);
        float2 c0 = __half22float2(*(__half2*)&uc.x), c1 = __half22float2(*(__half2*)&uc.y);
        float2 d0 = __half22float2(*(__half2*)&ud.x), d1 = __half22float2(*(__half2*)&ud.y);
        acc.x += a0.x + b0.x + c0.x + d0.x;
        acc.y += a0.y + b0.y + c0.y + d0.y;
        acc.z += a1.x + b1.x + c1.x + d1.x;
        acc.w += a1.y + b1.y + c1.y + d1.y;
    }
    for (; j < s1; j++) {
        int s = csr[j];
        uint2 u = xh[(size_t)s * 32 + lane];
        float2 f0 = __half22float2(*(__half2*)&u.x), f1 = __half22float2(*(__half2*)&u.y);
        acc.x += f0.x; acc.y += f0.y; acc.z += f1.x; acc.w += f1.y;
    }
    acc.x *= di; acc.y *= di; acc.z *= di; acc.w *= di;

    // hi/lo fp16 split
    __half hx = __float2half_rn(acc.x), hy = __float2half_rn(acc.y);
    __half hz = __float2half_rn(acc.z), hw = __float2half_rn(acc.w);
    float lxf = acc.x - __half2float(hx), lyf = acc.y - __half2float(hy);
    float lzf = acc.z - __half2float(hz), lwf = acc.w - __half2float(hw);
    __half2 hp0 = __halves2half2(hx, hy), hp1 = __halves2half2(hz, hw);
    __half2 lp0 = __floats2half2_rn(lxf, lyf), lp1 = __floats2half2_rn(lzf, lwf);

    // fragment-layout offsets: lane j handles k = j*4..j*4+3
    const int tile = i >> 7;
    const int rb = (i >> 4) & 7;
    const int r16 = i & 15;
    const int kl = (lane & 3) * 4;
    const int lane_f = ((r16 & 7) << 2) + ((kl & 7) >> 1);
    const int reg = ((r16 >> 3) & 1) + ((kl >> 3) << 1);
    const size_t base = ((((size_t)tile * 8 + rb) * 8 + (lane >> 2)) << 8) + (size_t)(lane_f * 8 + reg * 2);

    __half* Ah = g_Ah[p]; __half* Al = g_Al[p];
    *(__half2*)&Ah[base]     = hp0;
    *(__half2*)&Ah[base + 8] = hp1;
    *(__half2*)&Al[base]     = lp0;
    *(__half2*)&Al[base + 8] = lp1;
}

// ---------------- launch 4: mma.sync split-fp16 GEMM + lrelu + segment_max epilogue ----------------
#define W_STRIDE 68
#define SMEM_GEMM ((2 * 128 * W_STRIDE + 128) * 4)

__global__ void __launch_bounds__(512, 2)
k_gemm_pool(const float* __restrict__ b0, const float* __restrict__ b1,
            const int* __restrict__ batch0, const int* __restrict__ batch1) {
    extern __shared__ uint32_t smem[];
    uint32_t* hiP = smem;                       // [128][W_STRIDE] u32 (k-pairs)
    uint32_t* loP = smem + 128 * W_STRIDE;
    float* s_bias = (float*)(smem + 2 * 128 * W_STRIDE);

    const int p = blockIdx.y, tile = blockIdx.x;
    const float* __restrict__ bias  = p ? b1 : b0;
    const int*   __restrict__ batch = p ? batch1 : batch0;
    const int tid = threadIdx.x, lane = tid & 31, w = tid >> 5;
    const int w_m = w & 7, nh = w >> 3;

    // stage pre-split W -> smem with pad (straight copy)
    {
        const uint32_t* srcH = (const uint32_t*)g_Wt[p][0];
        const uint32_t* srcL = (const uint32_t*)g_Wt[p][1];
        #pragma unroll
        for (int it = 0; it < 16; it++) {
            int idx = tid + it * 512;           // 8192 u32
            int n = idx >> 6, ku = idx & 63;
            hiP[n * W_STRIDE + ku] = srcH[idx];
            loP[n * W_STRIDE + ku] = srcL[idx];
        }
    }
    if (tid < 128) s_bias[tid] = bias[tid];
    __syncthreads();

    float acc[8][4];
    #pragma unroll
    for (int jj = 0; jj < 8; jj++)
        #pragma unroll
        for (int q = 0; q < 4; q++) acc[jj][q] = 0.f;

    const __half* Ah = g_Ah[p];
    const __half* Al = g_Al[p];
    const size_t abase = ((size_t)tile * 8 + w_m) * 8;
    #pragma unroll
    for (int kc = 0; kc < 8; kc++) {
        uint4 ah = *(const uint4*)&Ah[((abase + kc) << 8) + lane * 8];
        uint4 al = *(const uint4*)&Al[((abase + kc) << 8) + lane * 8];
        #pragma unroll
        for (int jj = 0; jj < 8; jj++) {
            int n = (nh * 8 + jj) * 8 + (lane >> 2);
            int ku = kc * 8 + (lane & 3);
            uint32_t b0h = hiP[n * W_STRIDE + ku], b1h = hiP[n * W_STRIDE + ku + 4];
            uint32_t b0l = loP[n * W_STRIDE + ku], b1l = loP[n * W_STRIDE + ku + 4];
            MMA4(acc[jj], ah, b0h, b1h);
            MMA4(acc[jj], ah, b0l, b1l);
            MMA4(acc[jj], al, b0h, b1h);
        }
    }

    // epilogue: segment_max into pool
    const int r_base = tile * 128 + w_m * 16;
    float* pool = &g_pool[p * NB * DIM];
    const bool full = (r_base + 15 < N_NODES);
    const bool any  = (r_base < N_NODES);
    int btA = any ? batch[r_base] : -1;
    int btB = full ? batch[r_base + 15] : -2;

    if (full && btA == btB) {
        #pragma unroll
        for (int jj = 0; jj < 8; jj++) {
            float m0 = fmaxf(acc[jj][0], acc[jj][2]);
            float m1 = fmaxf(acc[jj][1], acc[jj][3]);
            #pragma unroll
            for (int o = 4; o <= 16; o <<= 1) {
                m0 = fmaxf(m0, __shfl_xor_sync(0xffffffffu, m0, o));
                m1 = fmaxf(m1, __shfl_xor_sync(0xffffffffu, m1, o));
            }
            if ((lane >> 2) == 0) {
                int c = (nh * 8 + jj) * 8 + (lane & 3) * 2;
                atomicMaxFloat(&pool[btA * DIM + c],     lrelu(m0 + s_bias[c]));
                atomicMaxFloat(&pool[btA * DIM + c + 1], lrelu(m1 + s_bias[c + 1]));
            }
        }
    } else if (any) {
        int r0 = r_base + (lane >> 2), r1 = r0 + 8;
        int bt0 = (r0 < N_NODES) ? batch[r0] : -1;
        int bt1 = (r1 < N_NODES) ? batch[r1] : -1;
        #pragma unroll
        for (int jj = 0; jj < 8; jj++) {
            int c = (nh * 8 + jj) * 8 + (lane & 3) * 2;
            if (bt0 >= 0) {
                atomicMaxFloat(&pool[bt0 * DIM + c],     lrelu(acc[jj][0] + s_bias[c]));
                atomicMaxFloat(&pool[bt0 * DIM + c + 1], lrelu(acc[jj][1] + s_bias[c + 1]));
            }
            if (bt1 >= 0) {
                atomicMaxFloat(&pool[bt1 * DIM + c],     lrelu(acc[jj][2] + s_bias[c]));
                atomicMaxFloat(&pool[bt1 * DIM + c + 1], lrelu(acc[jj][3] + s_bias[c + 1]));
            }
        }
    }
}

// ---------------- tail MLPs (tiny) ----------------
__global__ void k_fcp(const float* __restrict__ W1, const float* __restrict__ b1,
                      const float* __restrict__ W2, const float* __restrict__ b2) {
    int p = blockIdx.y, r = blockIdx.x, d = threadIdx.x;
    __shared__ float prow[128];
    prow[d] = g_pool[p * NB * DIM + r * 128 + d];
    __syncthreads();
    const float* W = p ? W2 : W1;
    const float* bb = p ? b2 : b1;
    float s = bb[d];
    #pragma unroll 8
    for (int k = 0; k < 128; k++) s += prow[k] * W[k * 128 + d];
    g_gp[p * NB * DIM + r * 128 + d] = lrelu(s);
}

__global__ void k_fc1(const float* __restrict__ W, const float* __restrict__ b) {
    int r = blockIdx.x, d = threadIdx.x;
    __shared__ float in[256];
    in[d] = (d < 128) ? g_gp[r * 128 + d] : g_gp[NB * DIM + r * 128 + (d - 128)];
    __syncthreads();
    float s = b[d];
    #pragma unroll 8
    for (int k = 0; k < 256; k++) s += in[k] * W[k * 256 + d];
    g_c1[r * 256 + d] = lrelu(s);
}

__global__ void k_fc2(const float* __restrict__ W, const float* __restrict__ b) {
    int r = blockIdx.x, d = threadIdx.x;
    __shared__ float in[256];
    for (int k = d; k < 256; k += 64) in[k] = g_c1[r * 256 + k];
    __syncthreads();
    float s = b[d];
    #pragma unroll 8
    for (int k = 0; k < 256; k++) s += in[k] * W[k * 64 + d];
    g_c2[r * 64 + d] = lrelu(s);
}

__global__ void k_out(const float* __restrict__ W, const float* __restrict__ b,
                      float* __restrict__ out) {
    int r = threadIdx.x;
    float s = b[0];
    #pragma unroll
    for (int k = 0; k < 64; k++) s += g_c2[r * 64 + k] * W[k];
    out[r] = 1.f / (1.f + expf(-s));
}

// ---------------- host launcher ----------------
extern "C" void kernel_launch(void* const* d_in, const int* in_sizes, int n_in,
                              void* d_out, int out_size) {
    int ix[2], ie[2], ib[2];
    if (in_sizes[1] == N_NODES * DIM) {
        ix[0] = 0; ix[1] = 1; ie[0] = 2; ie[1] = 3; ib[0] = 4; ib[1] = 5;   // dict order
    } else {
        ix[0] = 0; ie[0] = 1; ib[0] = 2; ix[1] = 3; ie[1] = 4; ib[1] = 5;   // signature order
    }
    const float* x0 = (const float*)d_in[ix[0]];
    const float* x1 = (const float*)d_in[ix[1]];
    const int* row0 = (const int*)d_in[ie[0]];
    const int* col0 = row0 + N_EDGES;
    const int* row1 = (const int*)d_in[ie[1]];
    const int* col1 = row1 + N_EDGES;
    const int* bat0 = (const int*)d_in[ib[0]];
    const int* bat1 = (const int*)d_in[ib[1]];

    const float* convW0 = (const float*)d_in[6];
    const float* convB0 = (const float*)d_in[7];
    const float* convW1 = (const float*)d_in[8];
    const float* convB1 = (const float*)d_in[9];
    const float* fcp1W = (const float*)d_in[10];
    const float* fcp1B = (const float*)d_in[11];
    const float* fcp2W = (const float*)d_in[12];
    const float* fcp2B = (const float*)d_in[13];
    const float* fc1W  = (const float*)d_in[14];
    const float* fc1B  = (const float*)d_in[15];
    const float* fc2W  = (const float*)d_in[16];
    const float* fc2B  = (const float*)d_in[17];
    const float* outW  = (const float*)d_in[18];
    const float* outB  = (const float*)d_in[19];

    static bool attr_done = false;
    if (!attr_done) {
        cudaFuncSetAttribute(k_gemm_pool, cudaFuncAttributeMaxDynamicSharedMemorySize, SMEM_GEMM);
        attr_done = true;
    }

    void* zPtr = nullptr;
    cudaGetSymbolAddress(&zPtr, g_z);
    cudaMemsetAsync(zPtr, 0, sizeof(Zeroed));

    k_count<<<dim3((N_EDGES + 255) / 256, 2), 256>>>(col0, col1);            // launch 0
    k_scan<<<dim3(SCAN_BLOCKS, 2), 1024>>>(x0, x1, convW0, convW1);          // launch 1
    k_fill<<<dim3((N_EDGES + 255) / 256, 2), 256>>>(row0, col0, row1, col1); // launch 2
    k_gather<<<dim3((N_NODES * 32 + 255) / 256, 2), 256>>>();                // launch 3 (captured)
    k_gemm_pool<<<dim3(TILES, 2), 512, SMEM_GEMM>>>(convB0, convB1, bat0, bat1);

    k_fcp<<<dim3(NB, 2), 128>>>(fcp1W, fcp1B, fcp2W, fcp2B);
    k_fc1<<<NB, 256>>>(fc1W, fc1B);
    k_fc2<<<NB, 64>>>(fc2W, fc2B);
    k_out<<<1, 128>>>(outW, outB, (float*)d_out);
}

// round 10
// speedup vs baseline: 1.1439x; 1.0710x over previous
#include <cuda_runtime.h>
#include <cuda_fp16.h>
#include <cstdint>
#include <math.h>
#include <float.h>

#define N_NODES 100000
#define N_EDGES 1600000
#define DIM 128
#define NB 128
#define NEG 0.01f
#define SCAN_BLOCKS 98   // ceil(100000/1024)
#define TILES 782        // ceil(100000/128)

// ---------------- scratch (static device globals; no allocation) ----------------
struct Zeroed {                              // zeroed by one cudaMemsetAsync per call
    int deg[2][N_NODES];
    unsigned long long look[2][SCAN_BLOCKS]; // lookback descriptors: (flag<<62)|value
};
__device__ Zeroed g_z;
__device__ __align__(16) uint2 g_xh[2][(size_t)N_NODES * 32]; // pre-scaled x̂ fp16 (dinv[src]*x), 4 halves/lane
__device__ float  g_dinv[2][N_NODES];
__device__ int    g_offs[2][N_NODES + 1];
__device__ int    g_cursor[2][N_NODES];
__device__ int    g_csr[2][N_EDGES];
// A operand in mma-fragment layout: frag (tile, rb(8), kc(8)) = 256 halves, thread-contiguous
__device__ __align__(16) __half g_Ah[2][(size_t)TILES * 64 * 256];
__device__ __align__(16) __half g_Al[2][(size_t)TILES * 64 * 256];
__device__ float g_pool[2 * NB * DIM];
__device__ float g_gp[2 * NB * DIM];
__device__ float g_c1[NB * 256];
__device__ float g_c2[NB * 64];

__device__ __forceinline__ float lrelu(float v) { return v >= 0.f ? v : NEG * v; }

__device__ __forceinline__ void atomicMaxFloat(float* addr, float v) {
    if (v >= 0.f) atomicMax((int*)addr, __float_as_int(v));
    else          atomicMin((unsigned int*)addr, __float_as_uint(v));
}

// mma.sync m16n8k16 fp16 in / fp32 accum (sm_80 PTX; legal on compute_103)
#define MMA4(c, a, bb0, bb1) \
    asm volatile("mma.sync.aligned.m16n8k16.row.col.f32.f16.f16.f32 " \
        "{%0,%1,%2,%3}, {%4,%5,%6,%7}, {%8,%9}, {%0,%1,%2,%3};" \
        : "+f"((c)[0]), "+f"((c)[1]), "+f"((c)[2]), "+f"((c)[3]) \
        : "r"((a).x), "r"((a).y), "r"((a).z), "r"((a).w), "r"(bb0), "r"(bb1))

// ---------------- launch 0: degree count ----------------
__global__ void k_count(const int* __restrict__ col0, const int* __restrict__ col1) {
    int p = blockIdx.y;
    const int* col = p ? col1 : col0;
    int e = blockIdx.x * blockDim.x + threadIdx.x;
    if (e < N_EDGES) atomicAdd(&g_z.deg[p][col[e]], 1);
}

// ---------------- launch 1: scan (decoupled lookback) + dinv + cursor + pool init + x̂ transcode ----------------
__global__ void k_scan(const float* __restrict__ x0, const float* __restrict__ x1) {
    __shared__ int sh[1024];
    __shared__ int sE;
    const int p = blockIdx.y;
    const int b = blockIdx.x;
    const int t = threadIdx.x;
    const int i = b * 1024 + t;
    const int lane = t & 31;

    int v = (i < N_NODES) ? g_z.deg[p][i] : 0;
    if (i < N_NODES) g_dinv[p][i] = rsqrtf((float)(v + 1));   // +1 self loop
    sh[t] = v;
    __syncthreads();
    #pragma unroll
    for (int off = 1; off < 1024; off <<= 1) {
        int x = (t >= off) ? sh[t - off] : 0;
        __syncthreads();
        sh[t] += x;
        __syncthreads();
    }
    const int total = sh[1023];

    if (b > 0 && t == 0)
        *(volatile unsigned long long*)&g_z.look[p][b] = (1ULL << 62) | (unsigned)total;
    if (t < 32) {   // warp 0 resolves exclusive prefix E
        int E = 0;
        if (b > 0) {
            int base = b - 1;
            int accum = 0;
            bool done = false;
            while (!done) {
                int idx = base - lane;
                unsigned long long w = (idx >= 0)
                    ? *(volatile unsigned long long*)&g_z.look[p][idx]
                    : (2ULL << 62);
                int flg = (int)(w >> 62);
                int val = (int)(w & 0xffffffffULL);
                unsigned m2 = __ballot_sync(0xffffffffu, flg == 2);
                unsigned m1 = __ballot_sync(0xffffffffu, flg >= 1);
                if (m2) {
                    int t2 = __ffs(m2) - 1;
                    unsigned below = (t2 == 0) ? 0u : ((1u << t2) - 1u);
                    if ((m1 & below) == below) {
                        int c = (lane <= t2) ? val : 0;
                        #pragma unroll
                        for (int o = 16; o; o >>= 1) c += __shfl_xor_sync(0xffffffffu, c, o);
                        accum += c;
                        done = true;
                    }
                } else if (m1 == 0xffffffffu) {
                    int c = (idx >= 0) ? val : 0;
                    #pragma unroll
                    for (int o = 16; o; o >>= 1) c += __shfl_xor_sync(0xffffffffu, c, o);
                    accum += c;
                    base -= 32;
                }
            }
            E = accum;
        }
        if (lane == 0) {
            *(volatile unsigned long long*)&g_z.look[p][b] = (2ULL << 62) | (unsigned)(E + total);
            sE = E;
        }
    }
    __syncthreads();
    const int E = sE;

    if (i < N_NODES) {
        int ex = E + sh[t] - v;
        g_offs[p][i] = ex;
        g_cursor[p][i] = ex;
    }
    if (b == 0 && t == 0) g_offs[p][N_NODES] = N_EDGES;
    if (b == 0) {
        #pragma unroll
        for (int it = 0; it < 16; it++)
            g_pool[p * NB * DIM + it * 1024 + t] = -FLT_MAX;
    }

    // ---- transcode tail: x̂ = dinv[src] * x (fp16), coalesced, 32 nodes/warp ----
    {
        const float4* xs = (const float4*)(p ? x1 : x0);
        const int w = t >> 5;
        const int nb = b * 1024 + w * 32;
        for (int nd = 0; nd < 32; nd++) {
            int i2 = nb + nd;
            if (i2 >= N_NODES) break;
            float s = rsqrtf((float)(g_z.deg[p][i2] + 1));
            float4 xv = xs[(size_t)i2 * 32 + lane];
            __half2 h0 = __floats2half2_rn(s * xv.x, s * xv.y);
            __half2 h1 = __floats2half2_rn(s * xv.z, s * xv.w);
            uint2 o;
            o.x = *(unsigned*)&h0; o.y = *(unsigned*)&h1;
            g_xh[p][(size_t)i2 * 32 + lane] = o;
        }
    }
}

// ---------------- launch 2: CSR fill ----------------
__global__ void k_fill(const int* __restrict__ row0, const int* __restrict__ col0,
                       const int* __restrict__ row1, const int* __restrict__ col1) {
    int p = blockIdx.y;
    const int* row = p ? row1 : row0;
    const int* col = p ? col1 : col0;
    int e = blockIdx.x * blockDim.x + threadIdx.x;
    if (e < N_EDGES) {
        int d = col[e];
        int pos = atomicAdd(&g_cursor[p][d], 1);
        g_csr[p][pos] = row[e];
    }
}

// ---------------- launch 3 (CAPTURED): gather (pre-scaled fp16) -> mma-frag hi/lo ----------------
__global__ void k_gather() {
    int p = blockIdx.y;
    const char*  xb  = (const char*)g_xh[p];     // byte base; row = 256B
    const int*   csr = g_csr[p];

    int gw = (blockIdx.x * blockDim.x + threadIdx.x) >> 5;
    int lane = threadIdx.x & 31;
    if (gw >= N_NODES) return;
    const int i = gw;
    const float di = g_dinv[p][i];
    const unsigned lb = (unsigned)lane * 8u;     // lane byte offset within row

    float4 acc;
    {
        uint2 u = *(const uint2*)(xb + (unsigned)i * 256u + lb);   // self term
        float2 fa = __half22float2(*(__half2*)&u.x), fb = __half22float2(*(__half2*)&u.y);
        acc.x = fa.x; acc.y = fa.y; acc.z = fb.x; acc.w = fb.y;
    }

    int j = g_offs[p][i];
    const int s1 = g_offs[p][i + 1];
    for (; j + 4 <= s1; j += 4) {
        unsigned oa = (unsigned)csr[j]     * 256u + lb;
        unsigned ob = (unsigned)csr[j + 1] * 256u + lb;
        unsigned oc = (unsigned)csr[j + 2] * 256u + lb;
        unsigned od = (unsigned)csr[j + 3] * 256u + lb;
        uint2 ua = *(const uint2*)(xb + oa);
        uint2 ub = *(const uint2*)(xb + ob);
        uint2 uc = *(const uint2*)(xb + oc);
        uint2 ud = *(const uint2*)(xb + od);
        float2 a0 = __half22float2(*(__half2*)&ua.x), a1 = __half22float2(*(__half2*)&ua.y);
        float2 b0 = __half22float2(*(__half2*)&ub.x), b1 = __half22float2(*(__half2*)&ub.y);
        float2 c0 = __half22float2(*(__half2*)&uc.x), c1 = __half22float2(*(__half2*)&uc.y);
        float2 d0 = __half22float2(*(__half2*)&ud.x), d1 = __half22float2(*(__half2*)&ud.y);
        acc.x += a0.x + b0.x + c0.x + d0.x;
        acc.y += a0.y + b0.y + c0.y + d0.y;
        acc.z += a1.x + b1.x + c1.x + d1.x;
        acc.w += a1.y + b1.y + c1.y + d1.y;
    }
    for (; j < s1; j++) {
        uint2 u = *(const uint2*)(xb + (unsigned)csr[j] * 256u + lb);
        float2 f0 = __half22float2(*(__half2*)&u.x), f1 = __half22float2(*(__half2*)&u.y);
        acc.x += f0.x; acc.y += f0.y; acc.z += f1.x; acc.w += f1.y;
    }
    acc.x *= di; acc.y *= di; acc.z *= di; acc.w *= di;

    // hi/lo fp16 split
    __half hx = __float2half_rn(acc.x), hy = __float2half_rn(acc.y);
    __half hz = __float2half_rn(acc.z), hw = __float2half_rn(acc.w);
    float lxf = acc.x - __half2float(hx), lyf = acc.y - __half2float(hy);
    float lzf = acc.z - __half2float(hz), lwf = acc.w - __half2float(hw);
    __half2 hp0 = __halves2half2(hx, hy), hp1 = __halves2half2(hz, hw);
    __half2 lp0 = __floats2half2_rn(lxf, lyf), lp1 = __floats2half2_rn(lzf, lwf);

    // fragment-layout offsets: lane j handles k = j*4..j*4+3
    const int tile = i >> 7;
    const int rb = (i >> 4) & 7;          // 16-row frag within tile
    const int r16 = i & 15;
    const int kc = lane >> 2;             // k-chunk
    const int kl = (lane & 3) * 4;        // k within chunk (0,4,8,12)
    const int lane_f = ((r16 & 7) << 2) + ((kl & 7) >> 1);
    const int reg = ((r16 >> 3) & 1) + ((kl >> 3) << 1);
    const size_t base = ((((size_t)tile * 8 + rb) * 8 + kc) << 8) + (size_t)(lane_f * 8 + reg * 2);

    __half* Ah = g_Ah[p]; __half* Al = g_Al[p];
    *(__half2*)&Ah[base]     = hp0;       // (k, k+1)
    *(__half2*)&Ah[base + 8] = hp1;       // (k+2, k+3)
    *(__half2*)&Al[base]     = lp0;
    *(__half2*)&Al[base + 8] = lp1;
}

// ---------------- launch 4: mma.sync split-fp16 GEMM + lrelu + segment_max epilogue ----------------
// 512 threads: 16 warps = 8 M-frags x 2 N-halves. W staged in smem [n][k] hi/lo, stride 68 u32.
#define W_STRIDE 68
#define SMEM_GEMM ((2 * 128 * W_STRIDE + 128) * 4)

__global__ void __launch_bounds__(512, 2)
k_gemm_pool(const float* __restrict__ W0, const float* __restrict__ b0,
            const float* __restrict__ W1, const float* __restrict__ b1,
            const int* __restrict__ batch0, const int* __restrict__ batch1) {
    extern __shared__ uint32_t smem[];
    uint32_t* hiP = smem;                       // [128][W_STRIDE] u32 (k-pairs)
    uint32_t* loP = smem + 128 * W_STRIDE;
    float* s_bias = (float*)(smem + 2 * 128 * W_STRIDE);

    const int p = blockIdx.y, tile = blockIdx.x;
    const float* __restrict__ W     = p ? W1 : W0;
    const float* __restrict__ bias  = p ? b1 : b0;
    const int*   __restrict__ batch = p ? batch1 : batch0;
    const int tid = threadIdx.x, lane = tid & 31, w = tid >> 5;
    const int w_m = w & 7, nh = w >> 3;

    // stage W -> smem transposed [n][k] fp16 hi/lo
    __half* hiH = (__half*)hiP;
    __half* loH = (__half*)loP;
    #pragma unroll
    for (int it = 0; it < 32; it++) {
        int idx = tid + it * 512;               // 16384 elems
        int k = idx >> 7, n = idx & 127;
        float wv = W[idx];
        __half hh = __float2half_rn(wv);
        __half hl = __float2half_rn(wv - __half2float(hh));
        hiH[n * (2 * W_STRIDE) + k] = hh;
        loH[n * (2 * W_STRIDE) + k] = hl;
    }
    if (tid < 128) s_bias[tid] = bias[tid];
    __syncthreads();

    float acc[8][4];
    #pragma unroll
    for (int jj = 0; jj < 8; jj++)
        #pragma unroll
        for (int q = 0; q < 4; q++) acc[jj][q] = 0.f;

    const __half* Ah = g_Ah[p];
    const __half* Al = g_Al[p];
    const size_t abase = ((size_t)tile * 8 + w_m) * 8;
    #pragma unroll
    for (int kc = 0; kc < 8; kc++) {
        uint4 ah = *(const uint4*)&Ah[((abase + kc) << 8) + lane * 8];
        uint4 al = *(const uint4*)&Al[((abase + kc) << 8) + lane * 8];
        #pragma unroll
        for (int jj = 0; jj < 8; jj++) {
            int n = (nh * 8 + jj) * 8 + (lane >> 2);
            int ku = kc * 8 + (lane & 3);
            uint32_t b0h = hiP[n * W_STRIDE + ku], b1h = hiP[n * W_STRIDE + ku + 4];
            uint32_t b0l = loP[n * W_STRIDE + ku], b1l = loP[n * W_STRIDE + ku + 4];
            MMA4(acc[jj], ah, b0h, b1h);
            MMA4(acc[jj], ah, b0l, b1l);
            MMA4(acc[jj], al, b0h, b1h);
        }
    }

    // epilogue: segment_max into pool
    const int r_base = tile * 128 + w_m * 16;
    float* pool = &g_pool[p * NB * DIM];
    const bool full = (r_base + 15 < N_NODES);
    const bool any  = (r_base < N_NODES);
    int btA = any ? batch[r_base] : -1;
    int btB = full ? batch[r_base + 15] : -2;

    if (full && btA == btB) {
        #pragma unroll
        for (int jj = 0; jj < 8; jj++) {
            float m0 = fmaxf(acc[jj][0], acc[jj][2]);
            float m1 = fmaxf(acc[jj][1], acc[jj][3]);
            #pragma unroll
            for (int o = 4; o <= 16; o <<= 1) {
                m0 = fmaxf(m0, __shfl_xor_sync(0xffffffffu, m0, o));
                m1 = fmaxf(m1, __shfl_xor_sync(0xffffffffu, m1, o));
            }
            if ((lane >> 2) == 0) {
                int c = (nh * 8 + jj) * 8 + (lane & 3) * 2;
                atomicMaxFloat(&pool[btA * DIM + c],     lrelu(m0 + s_bias[c]));
                atomicMaxFloat(&pool[btA * DIM + c + 1], lrelu(m1 + s_bias[c + 1]));
            }
        }
    } else if (any) {
        int r0 = r_base + (lane >> 2), r1 = r0 + 8;
        int bt0 = (r0 < N_NODES) ? batch[r0] : -1;
        int bt1 = (r1 < N_NODES) ? batch[r1] : -1;
        #pragma unroll
        for (int jj = 0; jj < 8; jj++) {
            int c = (nh * 8 + jj) * 8 + (lane & 3) * 2;
            if (bt0 >= 0) {
                atomicMaxFloat(&pool[bt0 * DIM + c],     lrelu(acc[jj][0] + s_bias[c]));
                atomicMaxFloat(&pool[bt0 * DIM + c + 1], lrelu(acc[jj][1] + s_bias[c + 1]));
            }
            if (bt1 >= 0) {
                atomicMaxFloat(&pool[bt1 * DIM + c],     lrelu(acc[jj][2] + s_bias[c]));
                atomicMaxFloat(&pool[bt1 * DIM + c + 1], lrelu(acc[jj][3] + s_bias[c + 1]));
            }
        }
    }
}

// ---------------- tail MLPs (tiny) ----------------
__global__ void k_fcp(const float* __restrict__ W1, const float* __restrict__ b1,
                      const float* __restrict__ W2, const float* __restrict__ b2) {
    int p = blockIdx.y, r = blockIdx.x, d = threadIdx.x;
    __shared__ float prow[128];
    prow[d] = g_pool[p * NB * DIM + r * 128 + d];
    __syncthreads();
    const float* W = p ? W2 : W1;
    const float* bb = p ? b2 : b1;
    float s = bb[d];
    #pragma unroll 8
    for (int k = 0; k < 128; k++) s += prow[k] * W[k * 128 + d];
    g_gp[p * NB * DIM + r * 128 + d] = lrelu(s);
}

__global__ void k_fc1(const float* __restrict__ W, const float* __restrict__ b) {
    int r = blockIdx.x, d = threadIdx.x;
    __shared__ float in[256];
    in[d] = (d < 128) ? g_gp[r * 128 + d] : g_gp[NB * DIM + r * 128 + (d - 128)];
    __syncthreads();
    float s = b[d];
    #pragma unroll 8
    for (int k = 0; k < 256; k++) s += in[k] * W[k * 256 + d];
    g_c1[r * 256 + d] = lrelu(s);
}

__global__ void k_fc2(const float* __restrict__ W, const float* __restrict__ b) {
    int r = blockIdx.x, d = threadIdx.x;
    __shared__ float in[256];
    for (int k = d; k < 256; k += 64) in[k] = g_c1[r * 256 + k];
    __syncthreads();
    float s = b[d];
    #pragma unroll 8
    for (int k = 0; k < 256; k++) s += in[k] * W[k * 64 + d];
    g_c2[r * 64 + d] = lrelu(s);
}

__global__ void k_out(const float* __restrict__ W, const float* __restrict__ b,
                      float* __restrict__ out) {
    int r = threadIdx.x;
    float s = b[0];
    #pragma unroll
    for (int k = 0; k < 64; k++) s += g_c2[r * 64 + k] * W[k];
    out[r] = 1.f / (1.f + expf(-s));
}

// ---------------- host launcher ----------------
extern "C" void kernel_launch(void* const* d_in, const int* in_sizes, int n_in,
                              void* d_out, int out_size) {
    int ix[2], ie[2], ib[2];
    if (in_sizes[1] == N_NODES * DIM) {
        ix[0] = 0; ix[1] = 1; ie[0] = 2; ie[1] = 3; ib[0] = 4; ib[1] = 5;   // dict order
    } else {
        ix[0] = 0; ie[0] = 1; ib[0] = 2; ix[1] = 3; ie[1] = 4; ib[1] = 5;   // signature order
    }
    const float* x0 = (const float*)d_in[ix[0]];
    const float* x1 = (const float*)d_in[ix[1]];
    const int* row0 = (const int*)d_in[ie[0]];
    const int* col0 = row0 + N_EDGES;
    const int* row1 = (const int*)d_in[ie[1]];
    const int* col1 = row1 + N_EDGES;
    const int* bat0 = (const int*)d_in[ib[0]];
    const int* bat1 = (const int*)d_in[ib[1]];

    const float* convW0 = (const float*)d_in[6];
    const float* convB0 = (const float*)d_in[7];
    const float* convW1 = (const float*)d_in[8];
    const float* convB1 = (const float*)d_in[9];
    const float* fcp1W = (const float*)d_in[10];
    const float* fcp1B = (const float*)d_in[11];
    const float* fcp2W = (const float*)d_in[12];
    const float* fcp2B = (const float*)d_in[13];
    const float* fc1W  = (const float*)d_in[14];
    const float* fc1B  = (const float*)d_in[15];
    const float* fc2W  = (const float*)d_in[16];
    const float* fc2B  = (const float*)d_in[17];
    const float* outW  = (const float*)d_in[18];
    const float* outB  = (const float*)d_in[19];

    static bool attr_done = false;
    if (!attr_done) {
        cudaFuncSetAttribute(k_gemm_pool, cudaFuncAttributeMaxDynamicSharedMemorySize, SMEM_GEMM);
        attr_done = true;
    }

    void* zPtr = nullptr;
    cudaGetSymbolAddress(&zPtr, g_z);
    cudaMemsetAsync(zPtr, 0, sizeof(Zeroed));

    k_count<<<dim3((N_EDGES + 255) / 256, 2), 256>>>(col0, col1);            // launch 0
    k_scan<<<dim3(SCAN_BLOCKS, 2), 1024>>>(x0, x1);                          // launch 1
    k_fill<<<dim3((N_EDGES + 255) / 256, 2), 256>>>(row0, col0, row1, col1); // launch 2
    k_gather<<<dim3((N_NODES * 32 + 255) / 256, 2), 256>>>();                // launch 3 (captured)
    k_gemm_pool<<<dim3(TILES, 2), 512, SMEM_GEMM>>>(convW0, convB0, convW1, convB1, bat0, bat1);

    k_fcp<<<dim3(NB, 2), 128>>>(fcp1W, fcp1B, fcp2W, fcp2B);
    k_fc1<<<NB, 256>>>(fc1W, fc1B);
    k_fc2<<<NB, 64>>>(fc2W, fc2B);
    k_out<<<1, 128>>>(outW, outB, (float*)d_out);
}

// round 11
// speedup vs baseline: 1.2147x; 1.0619x over previous
#include <cuda_runtime.h>
#include <cuda_fp16.h>
#include <cstdint>
#include <math.h>
#include <float.h>

#define N_NODES 100000
#define N_EDGES 1600000
#define DIM 128
#define NB 128
#define NEG 0.01f
#define PREP_BLOCKS 98   // ceil(100000/1024)
#define TILES 782        // ceil(100000/128)
#define CAP 128          // bucket capacity per node (mean deg 16; P(>=128) ~ 0)

// ---------------- scratch (static device globals; no allocation) ----------------
__device__ int g_deg[2][N_NODES];            // zeroed by one cudaMemsetAsync per call
__device__ __align__(16) uint2 g_xh[2][(size_t)N_NODES * 32]; // pre-scaled x̂ fp16 (dinv[src]*x)
__device__ float  g_dinv[2][N_NODES];
__device__ int    g_buck[2][(size_t)N_NODES * CAP];           // padded CSR buckets (src per slot)
// A operand in mma-fragment layout: frag (tile, rb(8), kc(8)) = 256 halves, thread-contiguous
__device__ __align__(16) __half g_Ah[2][(size_t)TILES * 64 * 256];
__device__ __align__(16) __half g_Al[2][(size_t)TILES * 64 * 256];
__device__ float g_pool[2 * NB * DIM];
__device__ float g_gp[2 * NB * DIM];
__device__ float g_c1[NB * 256];
__device__ float g_c2[NB * 64];

__device__ __forceinline__ float lrelu(float v) { return v >= 0.f ? v : NEG * v; }

__device__ __forceinline__ void atomicMaxFloat(float* addr, float v) {
    if (v >= 0.f) atomicMax((int*)addr, __float_as_int(v));
    else          atomicMin((unsigned int*)addr, __float_as_uint(v));
}

// mma.sync m16n8k16 fp16 in / fp32 accum (sm_80 PTX; legal on compute_103)
#define MMA4(c, a, bb0, bb1) \
    asm volatile("mma.sync.aligned.m16n8k16.row.col.f32.f16.f16.f32 " \
        "{%0,%1,%2,%3}, {%4,%5,%6,%7}, {%8,%9}, {%0,%1,%2,%3};" \
        : "+f"((c)[0]), "+f"((c)[1]), "+f"((c)[2]), "+f"((c)[3]) \
        : "r"((a).x), "r"((a).y), "r"((a).z), "r"((a).w), "r"(bb0), "r"(bb1))

// ---------------- launch 1: bucket fill (count + scatter in one pass) ----------------
__global__ void k_fill(const int* __restrict__ row0, const int* __restrict__ col0,
                       const int* __restrict__ row1, const int* __restrict__ col1) {
    int p = blockIdx.y;
    const int* row = p ? row1 : row0;
    const int* col = p ? col1 : col0;
    int e = blockIdx.x * blockDim.x + threadIdx.x;
    if (e < N_EDGES) {
        int d = col[e];
        int pos = atomicAdd(&g_deg[p][d], 1);
        g_buck[p][(size_t)d * CAP + pos] = row[e];
    }
}

// ---------------- launch 2: dinv + pool init + x̂ transcode ----------------
__global__ void k_prep(const float* __restrict__ x0, const float* __restrict__ x1) {
    const int p = blockIdx.y;
    const int b = blockIdx.x;
    const int t = threadIdx.x;
    const int i = b * 1024 + t;
    const int lane = t & 31;

    if (i < N_NODES) g_dinv[p][i] = rsqrtf((float)(g_deg[p][i] + 1));   // +1 self loop
    if (b == 0) {
        #pragma unroll
        for (int it = 0; it < 16; it++)
            g_pool[p * NB * DIM + it * 1024 + t] = -FLT_MAX;
    }

    // transcode: x̂ = dinv[src] * x (fp16), coalesced, 32 nodes/warp
    {
        const float4* xs = (const float4*)(p ? x1 : x0);
        const int w = t >> 5;
        const int nb = b * 1024 + w * 32;
        for (int nd = 0; nd < 32; nd++) {
            int i2 = nb + nd;
            if (i2 >= N_NODES) break;
            float s = rsqrtf((float)(g_deg[p][i2] + 1));
            float4 xv = xs[(size_t)i2 * 32 + lane];
            __half2 h0 = __floats2half2_rn(s * xv.x, s * xv.y);
            __half2 h1 = __floats2half2_rn(s * xv.z, s * xv.w);
            uint2 o;
            o.x = *(unsigned*)&h0; o.y = *(unsigned*)&h1;
            g_xh[p][(size_t)i2 * 32 + lane] = o;
        }
    }
}

// ---------------- launch 3: gather (pre-scaled fp16) -> mma-frag hi/lo ----------------
__global__ void k_gather() {
    int p = blockIdx.y;
    const char* xb = (const char*)g_xh[p];       // byte base; row = 256B
    int gw = (blockIdx.x * blockDim.x + threadIdx.x) >> 5;
    int lane = threadIdx.x & 31;
    if (gw >= N_NODES) return;
    const int i = gw;
    const float di = g_dinv[p][i];
    const unsigned lb = (unsigned)lane * 8u;     // lane byte offset within row
    const int* csr = g_buck[p] + (size_t)i * CAP;

    float4 acc;
    {
        uint2 u = *(const uint2*)(xb + (unsigned)i * 256u + lb);   // self term
        float2 fa = __half22float2(*(__half2*)&u.x), fb = __half22float2(*(__half2*)&u.y);
        acc.x = fa.x; acc.y = fa.y; acc.z = fb.x; acc.w = fb.y;
    }

    int j = 0;
    const int s1 = g_deg[p][i];
    for (; j + 4 <= s1; j += 4) {
        unsigned oa = (unsigned)csr[j]     * 256u + lb;
        unsigned ob = (unsigned)csr[j + 1] * 256u + lb;
        unsigned oc = (unsigned)csr[j + 2] * 256u + lb;
        unsigned od = (unsigned)csr[j + 3] * 256u + lb;
        uint2 ua = *(const uint2*)(xb + oa);
        uint2 ub = *(const uint2*)(xb + ob);
        uint2 uc = *(const uint2*)(xb + oc);
        uint2 ud = *(const uint2*)(xb + od);
        float2 a0 = __half22float2(*(__half2*)&ua.x), a1 = __half22float2(*(__half2*)&ua.y);
        float2 b0 = __half22float2(*(__half2*)&ub.x), b1 = __half22float2(*(__half2*)&ub.y);
        float2 c0 = __half22float2(*(__half2*)&uc.x), c1 = __half22float2(*(__half2*)&uc.y);
        float2 d0 = __half22float2(*(__half2*)&ud.x), d1 = __half22float2(*(__half2*)&ud.y);
        acc.x += a0.x + b0.x + c0.x + d0.x;
        acc.y += a0.y + b0.y + c0.y + d0.y;
        acc.z += a1.x + b1.x + c1.x + d1.x;
        acc.w += a1.y + b1.y + c1.y + d1.y;
    }
    for (; j < s1; j++) {
        uint2 u = *(const uint2*)(xb + (unsigned)csr[j] * 256u + lb);
        float2 f0 = __half22float2(*(__half2*)&u.x), f1 = __half22float2(*(__half2*)&u.y);
        acc.x += f0.x; acc.y += f0.y; acc.z += f1.x; acc.w += f1.y;
    }
    acc.x *= di; acc.y *= di; acc.z *= di; acc.w *= di;

    // hi/lo fp16 split
    __half hx = __float2half_rn(acc.x), hy = __float2half_rn(acc.y);
    __half hz = __float2half_rn(acc.z), hw = __float2half_rn(acc.w);
    float lxf = acc.x - __half2float(hx), lyf = acc.y - __half2float(hy);
    float lzf = acc.z - __half2float(hz), lwf = acc.w - __half2float(hw);
    __half2 hp0 = __halves2half2(hx, hy), hp1 = __halves2half2(hz, hw);
    __half2 lp0 = __floats2half2_rn(lxf, lyf), lp1 = __floats2half2_rn(lzf, lwf);

    // fragment-layout offsets: lane j handles k = j*4..j*4+3
    const int tile = i >> 7;
    const int rb = (i >> 4) & 7;          // 16-row frag within tile
    const int r16 = i & 15;
    const int kc = lane >> 2;             // k-chunk
    const int kl = (lane & 3) * 4;        // k within chunk (0,4,8,12)
    const int lane_f = ((r16 & 7) << 2) + ((kl & 7) >> 1);
    const int reg = ((r16 >> 3) & 1) + ((kl >> 3) << 1);
    const size_t base = ((((size_t)tile * 8 + rb) * 8 + kc) << 8) + (size_t)(lane_f * 8 + reg * 2);

    __half* Ah = g_Ah[p]; __half* Al = g_Al[p];
    *(__half2*)&Ah[base]     = hp0;       // (k, k+1)
    *(__half2*)&Ah[base + 8] = hp1;       // (k+2, k+3)
    *(__half2*)&Al[base]     = lp0;
    *(__half2*)&Al[base + 8] = lp1;
}

// ---------------- launch 4 (CAPTURED): mma.sync split-fp16 GEMM + lrelu + segment_max ----------------
// 512 threads: 16 warps = 8 M-frags x 2 N-halves. W staged in smem [n][k] hi/lo, stride 68 u32.
#define W_STRIDE 68
#define SMEM_GEMM ((2 * 128 * W_STRIDE + 128) * 4)

__global__ void __launch_bounds__(512, 2)
k_gemm_pool(const float* __restrict__ W0, const float* __restrict__ b0,
            const float* __restrict__ W1, const float* __restrict__ b1,
            const int* __restrict__ batch0, const int* __restrict__ batch1) {
    extern __shared__ uint32_t smem[];
    uint32_t* hiP = smem;                       // [128][W_STRIDE] u32 (k-pairs)
    uint32_t* loP = smem + 128 * W_STRIDE;
    float* s_bias = (float*)(smem + 2 * 128 * W_STRIDE);

    const int p = blockIdx.y, tile = blockIdx.x;
    const float* __restrict__ W     = p ? W1 : W0;
    const float* __restrict__ bias  = p ? b1 : b0;
    const int*   __restrict__ batch = p ? batch1 : batch0;
    const int tid = threadIdx.x, lane = tid & 31, w = tid >> 5;
    const int w_m = w & 7, nh = w >> 3;

    // stage W -> smem transposed [n][k] fp16 hi/lo
    __half* hiH = (__half*)hiP;
    __half* loH = (__half*)loP;
    #pragma unroll
    for (int it = 0; it < 32; it++) {
        int idx = tid + it * 512;               // 16384 elems
        int k = idx >> 7, n = idx & 127;
        float wv = W[idx];
        __half hh = __float2half_rn(wv);
        __half hl = __float2half_rn(wv - __half2float(hh));
        hiH[n * (2 * W_STRIDE) + k] = hh;
        loH[n * (2 * W_STRIDE) + k] = hl;
    }
    if (tid < 128) s_bias[tid] = bias[tid];
    __syncthreads();

    float acc[8][4];
    #pragma unroll
    for (int jj = 0; jj < 8; jj++)
        #pragma unroll
        for (int q = 0; q < 4; q++) acc[jj][q] = 0.f;

    const __half* Ah = g_Ah[p];
    const __half* Al = g_Al[p];
    const size_t abase = ((size_t)tile * 8 + w_m) * 8;
    #pragma unroll
    for (int kc = 0; kc < 8; kc++) {
        uint4 ah = *(const uint4*)&Ah[((abase + kc) << 8) + lane * 8];
        uint4 al = *(const uint4*)&Al[((abase + kc) << 8) + lane * 8];
        #pragma unroll
        for (int jj = 0; jj < 8; jj++) {
            int n = (nh * 8 + jj) * 8 + (lane >> 2);
            int ku = kc * 8 + (lane & 3);
            uint32_t b0h = hiP[n * W_STRIDE + ku], b1h = hiP[n * W_STRIDE + ku + 4];
            uint32_t b0l = loP[n * W_STRIDE + ku], b1l = loP[n * W_STRIDE + ku + 4];
            MMA4(acc[jj], ah, b0h, b1h);
            MMA4(acc[jj], ah, b0l, b1l);
            MMA4(acc[jj], al, b0h, b1h);
        }
    }

    // epilogue: segment_max into pool
    const int r_base = tile * 128 + w_m * 16;
    float* pool = &g_pool[p * NB * DIM];
    const bool full = (r_base + 15 < N_NODES);
    const bool any  = (r_base < N_NODES);
    int btA = any ? batch[r_base] : -1;
    int btB = full ? batch[r_base + 15] : -2;

    if (full && btA == btB) {
        #pragma unroll
        for (int jj = 0; jj < 8; jj++) {
            float m0 = fmaxf(acc[jj][0], acc[jj][2]);
            float m1 = fmaxf(acc[jj][1], acc[jj][3]);
            #pragma unroll
            for (int o = 4; o <= 16; o <<= 1) {
                m0 = fmaxf(m0, __shfl_xor_sync(0xffffffffu, m0, o));
                m1 = fmaxf(m1, __shfl_xor_sync(0xffffffffu, m1, o));
            }
            if ((lane >> 2) == 0) {
                int c = (nh * 8 + jj) * 8 + (lane & 3) * 2;
                atomicMaxFloat(&pool[btA * DIM + c],     lrelu(m0 + s_bias[c]));
                atomicMaxFloat(&pool[btA * DIM + c + 1], lrelu(m1 + s_bias[c + 1]));
            }
        }
    } else if (any) {
        int r0 = r_base + (lane >> 2), r1 = r0 + 8;
        int bt0 = (r0 < N_NODES) ? batch[r0] : -1;
        int bt1 = (r1 < N_NODES) ? batch[r1] : -1;
        #pragma unroll
        for (int jj = 0; jj < 8; jj++) {
            int c = (nh * 8 + jj) * 8 + (lane & 3) * 2;
            if (bt0 >= 0) {
                atomicMaxFloat(&pool[bt0 * DIM + c],     lrelu(acc[jj][0] + s_bias[c]));
                atomicMaxFloat(&pool[bt0 * DIM + c + 1], lrelu(acc[jj][1] + s_bias[c + 1]));
            }
            if (bt1 >= 0) {
                atomicMaxFloat(&pool[bt1 * DIM + c],     lrelu(acc[jj][2] + s_bias[c]));
                atomicMaxFloat(&pool[bt1 * DIM + c + 1], lrelu(acc[jj][3] + s_bias[c + 1]));
            }
        }
    }
}

// ---------------- tail MLPs (tiny) ----------------
__global__ void k_fcp(const float* __restrict__ W1, const float* __restrict__ b1,
                      const float* __restrict__ W2, const float* __restrict__ b2) {
    int p = blockIdx.y, r = blockIdx.x, d = threadIdx.x;
    __shared__ float prow[128];
    prow[d] = g_pool[p * NB * DIM + r * 128 + d];
    __syncthreads();
    const float* W = p ? W2 : W1;
    const float* bb = p ? b2 : b1;
    float s = bb[d];
    #pragma unroll 8
    for (int k = 0; k < 128; k++) s += prow[k] * W[k * 128 + d];
    g_gp[p * NB * DIM + r * 128 + d] = lrelu(s);
}

__global__ void k_fc1(const float* __restrict__ W, const float* __restrict__ b) {
    int r = blockIdx.x, d = threadIdx.x;
    __shared__ float in[256];
    in[d] = (d < 128) ? g_gp[r * 128 + d] : g_gp[NB * DIM + r * 128 + (d - 128)];
    __syncthreads();
    float s = b[d];
    #pragma unroll 8
    for (int k = 0; k < 256; k++) s += in[k] * W[k * 256 + d];
    g_c1[r * 256 + d] = lrelu(s);
}

__global__ void k_fc2(const float* __restrict__ W, const float* __restrict__ b) {
    int r = blockIdx.x, d = threadIdx.x;
    __shared__ float in[256];
    for (int k = d; k < 256; k += 64) in[k] = g_c1[r * 256 + k];
    __syncthreads();
    float s = b[d];
    #pragma unroll 8
    for (int k = 0; k < 256; k++) s += in[k] * W[k * 64 + d];
    g_c2[r * 64 + d] = lrelu(s);
}

__global__ void k_out(const float* __restrict__ W, const float* __restrict__ b,
                      float* __restrict__ out) {
    int r = threadIdx.x;
    float s = b[0];
    #pragma unroll
    for (int k = 0; k < 64; k++) s += g_c2[r * 64 + k] * W[k];
    out[r] = 1.f / (1.f + expf(-s));
}

// ---------------- host launcher ----------------
extern "C" void kernel_launch(void* const* d_in, const int* in_sizes, int n_in,
                              void* d_out, int out_size) {
    int ix[2], ie[2], ib[2];
    if (in_sizes[1] == N_NODES * DIM) {
        ix[0] = 0; ix[1] = 1; ie[0] = 2; ie[1] = 3; ib[0] = 4; ib[1] = 5;   // dict order
    } else {
        ix[0] = 0; ie[0] = 1; ib[0] = 2; ix[1] = 3; ie[1] = 4; ib[1] = 5;   // signature order
    }
    const float* x0 = (const float*)d_in[ix[0]];
    const float* x1 = (const float*)d_in[ix[1]];
    const int* row0 = (const int*)d_in[ie[0]];
    const int* col0 = row0 + N_EDGES;
    const int* row1 = (const int*)d_in[ie[1]];
    const int* col1 = row1 + N_EDGES;
    const int* bat0 = (const int*)d_in[ib[0]];
    const int* bat1 = (const int*)d_in[ib[1]];

    const float* convW0 = (const float*)d_in[6];
    const float* convB0 = (const float*)d_in[7];
    const float* convW1 = (const float*)d_in[8];
    const float* convB1 = (const float*)d_in[9];
    const float* fcp1W = (const float*)d_in[10];
    const float* fcp1B = (const float*)d_in[11];
    const float* fcp2W = (const float*)d_in[12];
    const float* fcp2B = (const float*)d_in[13];
    const float* fc1W  = (const float*)d_in[14];
    const float* fc1B  = (const float*)d_in[15];
    const float* fc2W  = (const float*)d_in[16];
    const float* fc2B  = (const float*)d_in[17];
    const float* outW  = (const float*)d_in[18];
    const float* outB  = (const float*)d_in[19];

    static bool attr_done = false;
    if (!attr_done) {
        cudaFuncSetAttribute(k_gemm_pool, cudaFuncAttributeMaxDynamicSharedMemorySize, SMEM_GEMM);
        attr_done = true;
    }

    void* degPtr = nullptr;
    cudaGetSymbolAddress(&degPtr, g_deg);
    cudaMemsetAsync(degPtr, 0, 2 * N_NODES * sizeof(int));

    k_fill<<<dim3((N_EDGES + 255) / 256, 2), 256>>>(row0, col0, row1, col1); // launch 1
    k_prep<<<dim3(PREP_BLOCKS, 2), 1024>>>(x0, x1);                          // launch 2
    k_gather<<<dim3((N_NODES * 32 + 255) / 256, 2), 256>>>();                // launch 3
    k_gemm_pool<<<dim3(TILES, 2), 512, SMEM_GEMM>>>(convW0, convB0, convW1, convB1, bat0, bat1); // launch 4 (captured)

    k_fcp<<<dim3(NB, 2), 128>>>(fcp1W, fcp1B, fcp2W, fcp2B);
    k_fc1<<<NB, 256>>>(fc1W, fc1B);
    k_fc2<<<NB, 64>>>(fc2W, fc2B);
    k_out<<<1, 128>>>(outW, outB, (float*)d_out);
}

// round 12
// speedup vs baseline: 1.2485x; 1.0278x over previous
#include <cuda_runtime.h>
#include <cuda_fp16.h>
#include <cstdint>
#include <math.h>
#include <float.h>

#define N_NODES 100000
#define N_EDGES 1600000
#define DIM 128
#define NB 128
#define NEG 0.01f
#define PREP_BLOCKS 98   // ceil(100000/1024)
#define TILES 782        // ceil(100000/128)
#define CAP 128          // bucket capacity per node (mean deg 16; P(>=128) ~ 0)

// ---------------- scratch (static device globals; no allocation) ----------------
__device__ int g_deg[2][N_NODES];            // zeroed by one cudaMemsetAsync per call
__device__ __align__(16) uint2 g_xh[2][(size_t)N_NODES * 32]; // pre-scaled x̂ fp16 (dinv[src]*x)
__device__ float  g_dinv[2][N_NODES];
__device__ int    g_buck[2][(size_t)N_NODES * CAP];           // padded CSR buckets (src per slot)
// A operand in mma-fragment layout: frag (tile, rb(8), kc(8)) = 256 halves, thread-contiguous
__device__ __align__(16) __half g_Ah[2][(size_t)TILES * 64 * 256];
__device__ __align__(16) __half g_Al[2][(size_t)TILES * 64 * 256];
__device__ float g_pool[2 * NB * DIM];
__device__ float g_gp[2 * NB * DIM];
__device__ float g_c1[NB * 256];
__device__ float g_c2[NB * 64];

__device__ __forceinline__ float lrelu(float v) { return v >= 0.f ? v : NEG * v; }

__device__ __forceinline__ void atomicMaxFloat(float* addr, float v) {
    if (v >= 0.f) atomicMax((int*)addr, __float_as_int(v));
    else          atomicMin((unsigned int*)addr, __float_as_uint(v));
}

// mma.sync m16n8k16 fp16 in / fp32 accum (sm_80 PTX; legal on compute_103)
#define MMA4(c, a, bb0, bb1) \
    asm volatile("mma.sync.aligned.m16n8k16.row.col.f32.f16.f16.f32 " \
        "{%0,%1,%2,%3}, {%4,%5,%6,%7}, {%8,%9}, {%0,%1,%2,%3};" \
        : "+f"((c)[0]), "+f"((c)[1]), "+f"((c)[2]), "+f"((c)[3]) \
        : "r"((a).x), "r"((a).y), "r"((a).z), "r"((a).w), "r"(bb0), "r"(bb1))

// ---------------- launch 1: bucket fill (count + scatter in one pass) ----------------
__global__ void k_fill(const int* __restrict__ row0, const int* __restrict__ col0,
                       const int* __restrict__ row1, const int* __restrict__ col1) {
    int p = blockIdx.y;
    const int* row = p ? row1 : row0;
    const int* col = p ? col1 : col0;
    int e = blockIdx.x * blockDim.x + threadIdx.x;
    if (e < N_EDGES) {
        int d = col[e];
        int pos = atomicAdd(&g_deg[p][d], 1);
        g_buck[p][(size_t)d * CAP + pos] = row[e];
    }
}

// ---------------- launch 2: dinv + pool init + x̂ transcode ----------------
__global__ void k_prep(const float* __restrict__ x0, const float* __restrict__ x1) {
    const int p = blockIdx.y;
    const int b = blockIdx.x;
    const int t = threadIdx.x;
    const int i = b * 1024 + t;
    const int lane = t & 31;

    if (i < N_NODES) g_dinv[p][i] = rsqrtf((float)(g_deg[p][i] + 1));   // +1 self loop
    if (b == 0) {
        #pragma unroll
        for (int it = 0; it < 16; it++)
            g_pool[p * NB * DIM + it * 1024 + t] = -FLT_MAX;
    }

    // transcode: x̂ = dinv[src] * x (fp16), coalesced, 32 nodes/warp
    {
        const float4* xs = (const float4*)(p ? x1 : x0);
        const int w = t >> 5;
        const int nb = b * 1024 + w * 32;
        for (int nd = 0; nd < 32; nd++) {
            int i2 = nb + nd;
            if (i2 >= N_NODES) break;
            float s = rsqrtf((float)(g_deg[p][i2] + 1));
            float4 xv = xs[(size_t)i2 * 32 + lane];
            __half2 h0 = __floats2half2_rn(s * xv.x, s * xv.y);
            __half2 h1 = __floats2half2_rn(s * xv.z, s * xv.w);
            uint2 o;
            o.x = *(unsigned*)&h0; o.y = *(unsigned*)&h1;
            g_xh[p][(size_t)i2 * 32 + lane] = o;
        }
    }
}

// ---------------- launch 3: gather (pre-scaled fp16) -> mma-frag hi/lo ----------------
__global__ void k_gather() {
    int p = blockIdx.y;
    const char* xb = (const char*)g_xh[p];       // byte base; row = 256B
    int gw = (blockIdx.x * blockDim.x + threadIdx.x) >> 5;
    int lane = threadIdx.x & 31;
    if (gw >= N_NODES) return;
    const int i = gw;
    const float di = g_dinv[p][i];
    const unsigned lb = (unsigned)lane * 8u;     // lane byte offset within row
    const int* csr = g_buck[p] + (size_t)i * CAP;

    float4 acc;
    {
        uint2 u = *(const uint2*)(xb + (unsigned)i * 256u + lb);   // self term
        float2 fa = __half22float2(*(__half2*)&u.x), fb = __half22float2(*(__half2*)&u.y);
        acc.x = fa.x; acc.y = fa.y; acc.z = fb.x; acc.w = fb.y;
    }

    int j = 0;
    const int s1 = g_deg[p][i];
    for (; j + 4 <= s1; j += 4) {
        unsigned oa = (unsigned)csr[j]     * 256u + lb;
        unsigned ob = (unsigned)csr[j + 1] * 256u + lb;
        unsigned oc = (unsigned)csr[j + 2] * 256u + lb;
        unsigned od = (unsigned)csr[j + 3] * 256u + lb;
        uint2 ua = *(const uint2*)(xb + oa);
        uint2 ub = *(const uint2*)(xb + ob);
        uint2 uc = *(const uint2*)(xb + oc);
        uint2 ud = *(const uint2*)(xb + od);
        float2 a0 = __half22float2(*(__half2*)&ua.x), a1 = __half22float2(*(__half2*)&ua.y);
        float2 b0 = __half22float2(*(__half2*)&ub.x), b1 = __half22float2(*(__half2*)&ub.y);
        float2 c0 = __half22float2(*(__half2*)&uc.x), c1 = __half22float2(*(__half2*)&uc.y);
        float2 d0 = __half22float2(*(__half2*)&ud.x), d1 = __half22float2(*(__half2*)&ud.y);
        acc.x += a0.x + b0.x + c0.x + d0.x;
        acc.y += a0.y + b0.y + c0.y + d0.y;
        acc.z += a1.x + b1.x + c1.x + d1.x;
        acc.w += a1.y + b1.y + c1.y + d1.y;
    }
    for (; j < s1; j++) {
        uint2 u = *(const uint2*)(xb + (unsigned)csr[j] * 256u + lb);
        float2 f0 = __half22float2(*(__half2*)&u.x), f1 = __half22float2(*(__half2*)&u.y);
        acc.x += f0.x; acc.y += f0.y; acc.z += f1.x; acc.w += f1.y;
    }
    acc.x *= di; acc.y *= di; acc.z *= di; acc.w *= di;

    // hi/lo fp16 split
    __half hx = __float2half_rn(acc.x), hy = __float2half_rn(acc.y);
    __half hz = __float2half_rn(acc.z), hw = __float2half_rn(acc.w);
    float lxf = acc.x - __half2float(hx), lyf = acc.y - __half2float(hy);
    float lzf = acc.z - __half2float(hz), lwf = acc.w - __half2float(hw);
    __half2 hp0 = __halves2half2(hx, hy), hp1 = __halves2half2(hz, hw);
    __half2 lp0 = __floats2half2_rn(lxf, lyf), lp1 = __floats2half2_rn(lzf, lwf);

    // fragment-layout offsets: lane j handles k = j*4..j*4+3
    const int tile = i >> 7;
    const int rb = (i >> 4) & 7;          // 16-row frag within tile
    const int r16 = i & 15;
    const int kc = lane >> 2;             // k-chunk
    const int kl = (lane & 3) * 4;        // k within chunk (0,4,8,12)
    const int lane_f = ((r16 & 7) << 2) + ((kl & 7) >> 1);
    const int reg = ((r16 >> 3) & 1) + ((kl >> 3) << 1);
    const size_t base = ((((size_t)tile * 8 + rb) * 8 + kc) << 8) + (size_t)(lane_f * 8 + reg * 2);

    __half* Ah = g_Ah[p]; __half* Al = g_Al[p];
    *(__half2*)&Ah[base]     = hp0;       // (k, k+1)
    *(__half2*)&Ah[base + 8] = hp1;       // (k+2, k+3)
    *(__half2*)&Al[base]     = lp0;
    *(__half2*)&Al[base + 8] = lp1;
}

// ---------------- launch 4 (CAPTURED): mma.sync split-fp16 GEMM, frag-ordered W smem ----------------
// 512 threads: 16 warps = 8 M-frags x 2 N-halves. W in smem as uint4 frags:
// sW[nb(16)][kc(8)][lane(32)] = {b0h, b1h, b0l, b1l} -> one LDS.128 per (jj,kc).
#define SMEM_GEMM (4096 * 16 + 512)

__global__ void __launch_bounds__(512, 2)
k_gemm_pool(const float* __restrict__ W0, const float* __restrict__ b0,
            const float* __restrict__ W1, const float* __restrict__ b1,
            const int* __restrict__ batch0, const int* __restrict__ batch1) {
    extern __shared__ uint4 sW[];                // 4096 uint4 = 64KB
    float* s_bias = (float*)(sW + 4096);

    const int p = blockIdx.y, tile = blockIdx.x;
    const float* __restrict__ W     = p ? W1 : W0;
    const float* __restrict__ bias  = p ? b1 : b0;
    const int*   __restrict__ batch = p ? batch1 : batch0;
    const int tid = threadIdx.x, lane = tid & 31, w = tid >> 5;
    const int w_m = w & 7, nh = w >> 3;

    // stage W -> fragment-ordered smem (one-time, 8 uint4/thread)
    #pragma unroll
    for (int it = 0; it < 8; it++) {
        int idx = tid + it * 512;                // 0..4095
        int lane_s = idx & 31;
        int kc_s = (idx >> 5) & 7;
        int nb_s = idx >> 8;                     // 0..15
        int n = nb_s * 8 + (lane_s >> 2);
        int k0 = (kc_s * 8 + (lane_s & 3)) * 2;  // pairs at k0,k0+1 and k0+8,k0+9
        float w00 = W[k0 * 128 + n];
        float w01 = W[(k0 + 1) * 128 + n];
        float w10 = W[(k0 + 8) * 128 + n];
        float w11 = W[(k0 + 9) * 128 + n];
        __half h00 = __float2half_rn(w00), h01 = __float2half_rn(w01);
        __half h10 = __float2half_rn(w10), h11 = __float2half_rn(w11);
        __half2 ph0 = __halves2half2(h00, h01), ph1 = __halves2half2(h10, h11);
        __half2 pl0 = __floats2half2_rn(w00 - __half2float(h00), w01 - __half2float(h01));
        __half2 pl1 = __floats2half2_rn(w10 - __half2float(h10), w11 - __half2float(h11));
        uint4 frag;
        frag.x = *(unsigned*)&ph0; frag.y = *(unsigned*)&ph1;
        frag.z = *(unsigned*)&pl0; frag.w = *(unsigned*)&pl1;
        sW[idx] = frag;
    }
    if (tid < 128) s_bias[tid] = bias[tid];
    __syncthreads();

    float acc[8][4];
    #pragma unroll
    for (int jj = 0; jj < 8; jj++)
        #pragma unroll
        for (int q = 0; q < 4; q++) acc[jj][q] = 0.f;

    const __half* Ah = g_Ah[p];
    const __half* Al = g_Al[p];
    const size_t abase = ((size_t)tile * 8 + w_m) * 8;
    #pragma unroll
    for (int kc = 0; kc < 8; kc++) {
        uint4 ah = *(const uint4*)&Ah[((abase + kc) << 8) + lane * 8];
        uint4 al = *(const uint4*)&Al[((abase + kc) << 8) + lane * 8];
        #pragma unroll
        for (int jj = 0; jj < 8; jj++) {
            uint4 bf = sW[(((nh * 8 + jj) * 8 + kc) << 5) + lane];   // one LDS.128
            MMA4(acc[jj], ah, bf.x, bf.y);
            MMA4(acc[jj], ah, bf.z, bf.w);
            MMA4(acc[jj], al, bf.x, bf.y);
        }
    }

    // epilogue: segment_max into pool
    const int r_base = tile * 128 + w_m * 16;
    float* pool = &g_pool[p * NB * DIM];
    const bool full = (r_base + 15 < N_NODES);
    const bool any  = (r_base < N_NODES);
    int btA = any ? batch[r_base] : -1;
    int btB = full ? batch[r_base + 15] : -2;

    if (full && btA == btB) {
        #pragma unroll
        for (int jj = 0; jj < 8; jj++) {
            float m0 = fmaxf(acc[jj][0], acc[jj][2]);
            float m1 = fmaxf(acc[jj][1], acc[jj][3]);
            #pragma unroll
            for (int o = 4; o <= 16; o <<= 1) {
                m0 = fmaxf(m0, __shfl_xor_sync(0xffffffffu, m0, o));
                m1 = fmaxf(m1, __shfl_xor_sync(0xffffffffu, m1, o));
            }
            if ((lane >> 2) == 0) {
                int c = (nh * 8 + jj) * 8 + (lane & 3) * 2;
                atomicMaxFloat(&pool[btA * DIM + c],     lrelu(m0 + s_bias[c]));
                atomicMaxFloat(&pool[btA * DIM + c + 1], lrelu(m1 + s_bias[c + 1]));
            }
        }
    } else if (any) {
        int r0 = r_base + (lane >> 2), r1 = r0 + 8;
        int bt0 = (r0 < N_NODES) ? batch[r0] : -1;
        int bt1 = (r1 < N_NODES) ? batch[r1] : -1;
        #pragma unroll
        for (int jj = 0; jj < 8; jj++) {
            int c = (nh * 8 + jj) * 8 + (lane & 3) * 2;
            if (bt0 >= 0) {
                atomicMaxFloat(&pool[bt0 * DIM + c],     lrelu(acc[jj][0] + s_bias[c]));
                atomicMaxFloat(&pool[bt0 * DIM + c + 1], lrelu(acc[jj][1] + s_bias[c + 1]));
            }
            if (bt1 >= 0) {
                atomicMaxFloat(&pool[bt1 * DIM + c],     lrelu(acc[jj][2] + s_bias[c]));
                atomicMaxFloat(&pool[bt1 * DIM + c + 1], lrelu(acc[jj][3] + s_bias[c + 1]));
            }
        }
    }
}

// ---------------- tail MLPs (tiny) ----------------
__global__ void k_fcp(const float* __restrict__ W1, const float* __restrict__ b1,
                      const float* __restrict__ W2, const float* __restrict__ b2) {
    int p = blockIdx.y, r = blockIdx.x, d = threadIdx.x;
    __shared__ float prow[128];
    prow[d] = g_pool[p * NB * DIM + r * 128 + d];
    __syncthreads();
    const float* W = p ? W2 : W1;
    const float* bb = p ? b2 : b1;
    float s = bb[d];
    #pragma unroll 8
    for (int k = 0; k < 128; k++) s += prow[k] * W[k * 128 + d];
    g_gp[p * NB * DIM + r * 128 + d] = lrelu(s);
}

__global__ void k_fc1(const float* __restrict__ W, const float* __restrict__ b) {
    int r = blockIdx.x, d = threadIdx.x;
    __shared__ float in[256];
    in[d] = (d < 128) ? g_gp[r * 128 + d] : g_gp[NB * DIM + r * 128 + (d - 128)];
    __syncthreads();
    float s = b[d];
    #pragma unroll 8
    for (int k = 0; k < 256; k++) s += in[k] * W[k * 256 + d];
    g_c1[r * 256 + d] = lrelu(s);
}

__global__ void k_fc2(const float* __restrict__ W, const float* __restrict__ b) {
    int r = blockIdx.x, d = threadIdx.x;
    __shared__ float in[256];
    for (int k = d; k < 256; k += 64) in[k] = g_c1[r * 256 + k];
    __syncthreads();
    float s = b[d];
    #pragma unroll 8
    for (int k = 0; k < 256; k++) s += in[k] * W[k * 64 + d];
    g_c2[r * 64 + d] = lrelu(s);
}

__global__ void k_out(const float* __restrict__ W, const float* __restrict__ b,
                      float* __restrict__ out) {
    int r = threadIdx.x;
    float s = b[0];
    #pragma unroll
    for (int k = 0; k < 64; k++) s += g_c2[r * 64 + k] * W[k];
    out[r] = 1.f / (1.f + expf(-s));
}

// ---------------- host launcher ----------------
extern "C" void kernel_launch(void* const* d_in, const int* in_sizes, int n_in,
                              void* d_out, int out_size) {
    int ix[2], ie[2], ib[2];
    if (in_sizes[1] == N_NODES * DIM) {
        ix[0] = 0; ix[1] = 1; ie[0] = 2; ie[1] = 3; ib[0] = 4; ib[1] = 5;   // dict order
    } else {
        ix[0] = 0; ie[0] = 1; ib[0] = 2; ix[1] = 3; ie[1] = 4; ib[1] = 5;   // signature order
    }
    const float* x0 = (const float*)d_in[ix[0]];
    const float* x1 = (const float*)d_in[ix[1]];
    const int* row0 = (const int*)d_in[ie[0]];
    const int* col0 = row0 + N_EDGES;
    const int* row1 = (const int*)d_in[ie[1]];
    const int* col1 = row1 + N_EDGES;
    const int* bat0 = (const int*)d_in[ib[0]];
    const int* bat1 = (const int*)d_in[ib[1]];

    const float* convW0 = (const float*)d_in[6];
    const float* convB0 = (const float*)d_in[7];
    const float* convW1 = (const float*)d_in[8];
    const float* convB1 = (const float*)d_in[9];
    const float* fcp1W = (const float*)d_in[10];
    const float* fcp1B = (const float*)d_in[11];
    const float* fcp2W = (const float*)d_in[12];
    const float* fcp2B = (const float*)d_in[13];
    const float* fc1W  = (const float*)d_in[14];
    const float* fc1B  = (const float*)d_in[15];
    const float* fc2W  = (const float*)d_in[16];
    const float* fc2B  = (const float*)d_in[17];
    const float* outW  = (const float*)d_in[18];
    const float* outB  = (const float*)d_in[19];

    static bool attr_done = false;
    if (!attr_done) {
        cudaFuncSetAttribute(k_gemm_pool, cudaFuncAttributeMaxDynamicSharedMemorySize, SMEM_GEMM);
        attr_done = true;
    }

    void* degPtr = nullptr;
    cudaGetSymbolAddress(&degPtr, g_deg);
    cudaMemsetAsync(degPtr, 0, 2 * N_NODES * sizeof(int));

    k_fill<<<dim3((N_EDGES + 255) / 256, 2), 256>>>(row0, col0, row1, col1); // launch 1
    k_prep<<<dim3(PREP_BLOCKS, 2), 1024>>>(x0, x1);                          // launch 2
    k_gather<<<dim3((N_NODES * 32 + 255) / 256, 2), 256>>>();                // launch 3
    k_gemm_pool<<<dim3(TILES, 2), 512, SMEM_GEMM>>>(convW0, convB0, convW1, convB1, bat0, bat1); // launch 4 (captured)

    k_fcp<<<dim3(NB, 2), 128>>>(fcp1W, fcp1B, fcp2W, fcp2B);
    k_fc1<<<NB, 256>>>(fc1W, fc1B);
    k_fc2<<<NB, 64>>>(fc2W, fc2B);
    k_out<<<1, 128>>>(outW, outB, (float*)d_out);
}

// round 13
// speedup vs baseline: 1.3744x; 1.1009x over previous
#include <cuda_runtime.h>
#include <cuda_fp16.h>
#include <cstdint>
#include <math.h>
#include <float.h>

#define N_NODES 100000
#define N_EDGES 1600000
#define DIM 128
#define NB 128
#define NEG 0.01f
#define PREP_BLOCKS 98   // ceil(100000/1024)
#define TILES 782        // ceil(100000/128)
#define CAP 128          // bucket capacity per node (mean deg 16; P(>=128) ~ 0)

// ---------------- scratch (static device globals; no allocation) ----------------
__device__ int g_deg[2][N_NODES];            // zeroed by one cudaMemsetAsync per call
__device__ __align__(16) uint2 g_xh[2][(size_t)N_NODES * 32]; // pre-scaled x̂ fp16 (dinv[src]*x)
__device__ float  g_dinv[2][N_NODES];
__device__ int    g_buck[2][(size_t)N_NODES * CAP];           // padded CSR buckets (src per slot)
// A operand in mma-fragment layout: frag (tile, rb(8), kc(8)) = 256 halves, thread-contiguous
__device__ __align__(16) __half g_Ah[2][(size_t)TILES * 64 * 256];
__device__ float g_pool[2 * NB * DIM];
__device__ float g_gp[2 * NB * DIM];
__device__ float g_c1[NB * 256];
__device__ float g_c2[NB * 64];

__device__ __forceinline__ float lrelu(float v) { return v >= 0.f ? v : NEG * v; }

__device__ __forceinline__ void atomicMaxFloat(float* addr, float v) {
    if (v >= 0.f) atomicMax((int*)addr, __float_as_int(v));
    else          atomicMin((unsigned int*)addr, __float_as_uint(v));
}

// mma.sync m16n8k16 fp16 in / fp32 accum (sm_80 PTX; legal on compute_103)
#define MMA4(c, a, bb0, bb1) \
    asm volatile("mma.sync.aligned.m16n8k16.row.col.f32.f16.f16.f32 " \
        "{%0,%1,%2,%3}, {%4,%5,%6,%7}, {%8,%9}, {%0,%1,%2,%3};" \
        : "+f"((c)[0]), "+f"((c)[1]), "+f"((c)[2]), "+f"((c)[3]) \
        : "r"((a).x), "r"((a).y), "r"((a).z), "r"((a).w), "r"(bb0), "r"(bb1))

// ---------------- launch 1: bucket fill (count + scatter in one pass) ----------------
__global__ void k_fill(const int* __restrict__ row0, const int* __restrict__ col0,
                       const int* __restrict__ row1, const int* __restrict__ col1) {
    int p = blockIdx.y;
    const int* row = p ? row1 : row0;
    const int* col = p ? col1 : col0;
    int e = blockIdx.x * blockDim.x + threadIdx.x;
    if (e < N_EDGES) {
        int d = col[e];
        int pos = atomicAdd(&g_deg[p][d], 1);
        g_buck[p][(size_t)d * CAP + pos] = row[e];
    }
}

// ---------------- launch 2: dinv + pool init + x̂ transcode ----------------
__global__ void k_prep(const float* __restrict__ x0, const float* __restrict__ x1) {
    const int p = blockIdx.y;
    const int b = blockIdx.x;
    const int t = threadIdx.x;
    const int i = b * 1024 + t;
    const int lane = t & 31;

    if (i < N_NODES) g_dinv[p][i] = rsqrtf((float)(g_deg[p][i] + 1));   // +1 self loop
    if (b == 0) {
        #pragma unroll
        for (int it = 0; it < 16; it++)
            g_pool[p * NB * DIM + it * 1024 + t] = -FLT_MAX;
    }

    // transcode: x̂ = dinv[src] * x (fp16), coalesced, 32 nodes/warp
    {
        const float4* xs = (const float4*)(p ? x1 : x0);
        const int w = t >> 5;
        const int nb = b * 1024 + w * 32;
        for (int nd = 0; nd < 32; nd++) {
            int i2 = nb + nd;
            if (i2 >= N_NODES) break;
            float s = rsqrtf((float)(g_deg[p][i2] + 1));
            float4 xv = xs[(size_t)i2 * 32 + lane];
            __half2 h0 = __floats2half2_rn(s * xv.x, s * xv.y);
            __half2 h1 = __floats2half2_rn(s * xv.z, s * xv.w);
            uint2 o;
            o.x = *(unsigned*)&h0; o.y = *(unsigned*)&h1;
            g_xh[p][(size_t)i2 * 32 + lane] = o;
        }
    }
}

// ---------------- launch 3: gather (pre-scaled fp16) -> mma-frag fp16 A ----------------
__global__ void k_gather() {
    int p = blockIdx.y;
    const char* xb = (const char*)g_xh[p];       // byte base; row = 256B
    int gw = (blockIdx.x * blockDim.x + threadIdx.x) >> 5;
    int lane = threadIdx.x & 31;
    if (gw >= N_NODES) return;
    const int i = gw;
    const float di = g_dinv[p][i];
    const unsigned lb = (unsigned)lane * 8u;     // lane byte offset within row
    const int* csr = g_buck[p] + (size_t)i * CAP;

    float4 acc;
    {
        uint2 u = *(const uint2*)(xb + (unsigned)i * 256u + lb);   // self term
        float2 fa = __half22float2(*(__half2*)&u.x), fb = __half22float2(*(__half2*)&u.y);
        acc.x = fa.x; acc.y = fa.y; acc.z = fb.x; acc.w = fb.y;
    }

    int j = 0;
    const int s1 = g_deg[p][i];
    for (; j + 4 <= s1; j += 4) {
        unsigned oa = (unsigned)csr[j]     * 256u + lb;
        unsigned ob = (unsigned)csr[j + 1] * 256u + lb;
        unsigned oc = (unsigned)csr[j + 2] * 256u + lb;
        unsigned od = (unsigned)csr[j + 3] * 256u + lb;
        uint2 ua = *(const uint2*)(xb + oa);
        uint2 ub = *(const uint2*)(xb + ob);
        uint2 uc = *(const uint2*)(xb + oc);
        uint2 ud = *(const uint2*)(xb + od);
        float2 a0 = __half22float2(*(__half2*)&ua.x), a1 = __half22float2(*(__half2*)&ua.y);
        float2 b0 = __half22float2(*(__half2*)&ub.x), b1 = __half22float2(*(__half2*)&ub.y);
        float2 c0 = __half22float2(*(__half2*)&uc.x), c1 = __half22float2(*(__half2*)&uc.y);
        float2 d0 = __half22float2(*(__half2*)&ud.x), d1 = __half22float2(*(__half2*)&ud.y);
        acc.x += a0.x + b0.x + c0.x + d0.x;
        acc.y += a0.y + b0.y + c0.y + d0.y;
        acc.z += a1.x + b1.x + c1.x + d1.x;
        acc.w += a1.y + b1.y + c1.y + d1.y;
    }
    for (; j < s1; j++) {
        uint2 u = *(const uint2*)(xb + (unsigned)csr[j] * 256u + lb);
        float2 f0 = __half22float2(*(__half2*)&u.x), f1 = __half22float2(*(__half2*)&u.y);
        acc.x += f0.x; acc.y += f0.y; acc.z += f1.x; acc.w += f1.y;
    }
    acc.x *= di; acc.y *= di; acc.z *= di; acc.w *= di;

    __half2 hp0 = __floats2half2_rn(acc.x, acc.y);
    __half2 hp1 = __floats2half2_rn(acc.z, acc.w);

    // fragment-layout offsets: lane j handles k = j*4..j*4+3
    const int tile = i >> 7;
    const int rb = (i >> 4) & 7;          // 16-row frag within tile
    const int r16 = i & 15;
    const int kc = lane >> 2;             // k-chunk
    const int kl = (lane & 3) * 4;        // k within chunk (0,4,8,12)
    const int lane_f = ((r16 & 7) << 2) + ((kl & 7) >> 1);
    const int reg = ((r16 >> 3) & 1) + ((kl >> 3) << 1);
    const size_t base = ((((size_t)tile * 8 + rb) * 8 + kc) << 8) + (size_t)(lane_f * 8 + reg * 2);

    __half* Ah = g_Ah[p];
    *(__half2*)&Ah[base]     = hp0;       // (k, k+1)
    *(__half2*)&Ah[base + 8] = hp1;       // (k+2, k+3)
}

// ---------------- launch 4 (CAPTURED): mma.sync fp16-A / split-fp16-W GEMM ----------------
// 512 threads: 16 warps = 8 M-frags x 2 N-halves. W in smem as uint4 frags:
// sW[nb(16)][kc(8)][lane(32)] = {b0h, b1h, b0l, b1l} -> one LDS.128 per (jj,kc), 2 MMAs.
#define SMEM_GEMM (4096 * 16 + 512)

__global__ void __launch_bounds__(512, 2)
k_gemm_pool(const float* __restrict__ W0, const float* __restrict__ b0,
            const float* __restrict__ W1, const float* __restrict__ b1,
            const int* __restrict__ batch0, const int* __restrict__ batch1) {
    extern __shared__ uint4 sW[];                // 4096 uint4 = 64KB
    float* s_bias = (float*)(sW + 4096);

    const int p = blockIdx.y, tile = blockIdx.x;
    const float* __restrict__ W     = p ? W1 : W0;
    const float* __restrict__ bias  = p ? b1 : b0;
    const int*   __restrict__ batch = p ? batch1 : batch0;
    const int tid = threadIdx.x, lane = tid & 31, w = tid >> 5;
    const int w_m = w & 7, nh = w >> 3;

    // stage W -> fragment-ordered smem (one-time, 8 uint4/thread)
    #pragma unroll
    for (int it = 0; it < 8; it++) {
        int idx = tid + it * 512;                // 0..4095
        int lane_s = idx & 31;
        int kc_s = (idx >> 5) & 7;
        int nb_s = idx >> 8;                     // 0..15
        int n = nb_s * 8 + (lane_s >> 2);
        int k0 = (kc_s * 8 + (lane_s & 3)) * 2;  // pairs at k0,k0+1 and k0+8,k0+9
        float w00 = W[k0 * 128 + n];
        float w01 = W[(k0 + 1) * 128 + n];
        float w10 = W[(k0 + 8) * 128 + n];
        float w11 = W[(k0 + 9) * 128 + n];
        __half h00 = __float2half_rn(w00), h01 = __float2half_rn(w01);
        __half h10 = __float2half_rn(w10), h11 = __float2half_rn(w11);
        __half2 ph0 = __halves2half2(h00, h01), ph1 = __halves2half2(h10, h11);
        __half2 pl0 = __floats2half2_rn(w00 - __half2float(h00), w01 - __half2float(h01));
        __half2 pl1 = __floats2half2_rn(w10 - __half2float(h10), w11 - __half2float(h11));
        uint4 frag;
        frag.x = *(unsigned*)&ph0; frag.y = *(unsigned*)&ph1;
        frag.z = *(unsigned*)&pl0; frag.w = *(unsigned*)&pl1;
        sW[idx] = frag;
    }
    if (tid < 128) s_bias[tid] = bias[tid];
    __syncthreads();

    float acc[8][4];
    #pragma unroll
    for (int jj = 0; jj < 8; jj++)
        #pragma unroll
        for (int q = 0; q < 4; q++) acc[jj][q] = 0.f;

    const __half* Ah = g_Ah[p];
    const size_t abase = ((size_t)tile * 8 + w_m) * 8;
    #pragma unroll
    for (int kc = 0; kc < 8; kc++) {
        uint4 ah = *(const uint4*)&Ah[((abase + kc) << 8) + lane * 8];
        #pragma unroll
        for (int jj = 0; jj < 8; jj++) {
            uint4 bf = sW[(((nh * 8 + jj) * 8 + kc) << 5) + lane];   // one LDS.128
            MMA4(acc[jj], ah, bf.x, bf.y);   // A * W_hi
            MMA4(acc[jj], ah, bf.z, bf.w);   // A * W_lo
        }
    }

    // epilogue: segment_max into pool
    const int r_base = tile * 128 + w_m * 16;
    float* pool = &g_pool[p * NB * DIM];
    const bool full = (r_base + 15 < N_NODES);
    const bool any  = (r_base < N_NODES);
    int btA = any ? batch[r_base] : -1;
    int btB = full ? batch[r_base + 15] : -2;

    if (full && btA == btB) {
        #pragma unroll
        for (int jj = 0; jj < 8; jj++) {
            float m0 = fmaxf(acc[jj][0], acc[jj][2]);
            float m1 = fmaxf(acc[jj][1], acc[jj][3]);
            #pragma unroll
            for (int o = 4; o <= 16; o <<= 1) {
                m0 = fmaxf(m0, __shfl_xor_sync(0xffffffffu, m0, o));
                m1 = fmaxf(m1, __shfl_xor_sync(0xffffffffu, m1, o));
            }
            if ((lane >> 2) == 0) {
                int c = (nh * 8 + jj) * 8 + (lane & 3) * 2;
                atomicMaxFloat(&pool[btA * DIM + c],     lrelu(m0 + s_bias[c]));
                atomicMaxFloat(&pool[btA * DIM + c + 1], lrelu(m1 + s_bias[c + 1]));
            }
        }
    } else if (any) {
        int r0 = r_base + (lane >> 2), r1 = r0 + 8;
        int bt0 = (r0 < N_NODES) ? batch[r0] : -1;
        int bt1 = (r1 < N_NODES) ? batch[r1] : -1;
        #pragma unroll
        for (int jj = 0; jj < 8; jj++) {
            int c = (nh * 8 + jj) * 8 + (lane & 3) * 2;
            if (bt0 >= 0) {
                atomicMaxFloat(&pool[bt0 * DIM + c],     lrelu(acc[jj][0] + s_bias[c]));
                atomicMaxFloat(&pool[bt0 * DIM + c + 1], lrelu(acc[jj][1] + s_bias[c + 1]));
            }
            if (bt1 >= 0) {
                atomicMaxFloat(&pool[bt1 * DIM + c],     lrelu(acc[jj][2] + s_bias[c]));
                atomicMaxFloat(&pool[bt1 * DIM + c + 1], lrelu(acc[jj][3] + s_bias[c + 1]));
            }
        }
    }
}

// ---------------- tail MLPs (tiny) ----------------
__global__ void k_fcp(const float* __restrict__ W1, const float* __restrict__ b1,
                      const float* __restrict__ W2, const float* __restrict__ b2) {
    int p = blockIdx.y, r = blockIdx.x, d = threadIdx.x;
    __shared__ float prow[128];
    prow[d] = g_pool[p * NB * DIM + r * 128 + d];
    __syncthreads();
    const float* W = p ? W2 : W1;
    const float* bb = p ? b2 : b1;
    float s = bb[d];
    #pragma unroll 8
    for (int k = 0; k < 128; k++) s += prow[k] * W[k * 128 + d];
    g_gp[p * NB * DIM + r * 128 + d] = lrelu(s);
}

__global__ void k_fc1(const float* __restrict__ W, const float* __restrict__ b) {
    int r = blockIdx.x, d = threadIdx.x;
    __shared__ float in[256];
    in[d] = (d < 128) ? g_gp[r * 128 + d] : g_gp[NB * DIM + r * 128 + (d - 128)];
    __syncthreads();
    float s = b[d];
    #pragma unroll 8
    for (int k = 0; k < 256; k++) s += in[k] * W[k * 256 + d];
    g_c1[r * 256 + d] = lrelu(s);
}

__global__ void k_fc2(const float* __restrict__ W, const float* __restrict__ b) {
    int r = blockIdx.x, d = threadIdx.x;
    __shared__ float in[256];
    for (int k = d; k < 256; k += 64) in[k] = g_c1[r * 256 + k];
    __syncthreads();
    float s = b[d];
    #pragma unroll 8
    for (int k = 0; k < 256; k++) s += in[k] * W[k * 64 + d];
    g_c2[r * 64 + d] = lrelu(s);
}

__global__ void k_out(const float* __restrict__ W, const float* __restrict__ b,
                      float* __restrict__ out) {
    int r = threadIdx.x;
    float s = b[0];
    #pragma unroll
    for (int k = 0; k < 64; k++) s += g_c2[r * 64 + k] * W[k];
    out[r] = 1.f / (1.f + expf(-s));
}

// ---------------- host launcher ----------------
extern "C" void kernel_launch(void* const* d_in, const int* in_sizes, int n_in,
                              void* d_out, int out_size) {
    int ix[2], ie[2], ib[2];
    if (in_sizes[1] == N_NODES * DIM) {
        ix[0] = 0; ix[1] = 1; ie[0] = 2; ie[1] = 3; ib[0] = 4; ib[1] = 5;   // dict order
    } else {
        ix[0] = 0; ie[0] = 1; ib[0] = 2; ix[1] = 3; ie[1] = 4; ib[1] = 5;   // signature order
    }
    const float* x0 = (const float*)d_in[ix[0]];
    const float* x1 = (const float*)d_in[ix[1]];
    const int* row0 = (const int*)d_in[ie[0]];
    const int* col0 = row0 + N_EDGES;
    const int* row1 = (const int*)d_in[ie[1]];
    const int* col1 = row1 + N_EDGES;
    const int* bat0 = (const int*)d_in[ib[0]];
    const int* bat1 = (const int*)d_in[ib[1]];

    const float* convW0 = (const float*)d_in[6];
    const float* convB0 = (const float*)d_in[7];
    const float* convW1 = (const float*)d_in[8];
    const float* convB1 = (const float*)d_in[9];
    const float* fcp1W = (const float*)d_in[10];
    const float* fcp1B = (const float*)d_in[11];
    const float* fcp2W = (const float*)d_in[12];
    const float* fcp2B = (const float*)d_in[13];
    const float* fc1W  = (const float*)d_in[14];
    const float* fc1B  = (const float*)d_in[15];
    const float* fc2W  = (const float*)d_in[16];
    const float* fc2B  = (const float*)d_in[17];
    const float* outW  = (const float*)d_in[18];
    const float* outB  = (const float*)d_in[19];

    static bool attr_done = false;
    if (!attr_done) {
        cudaFuncSetAttribute(k_gemm_pool, cudaFuncAttributeMaxDynamicSharedMemorySize, SMEM_GEMM);
        attr_done = true;
    }

    void* degPtr = nullptr;
    cudaGetSymbolAddress(&degPtr, g_deg);
    cudaMemsetAsync(degPtr, 0, 2 * N_NODES * sizeof(int));

    k_fill<<<dim3((N_EDGES + 255) / 256, 2), 256>>>(row0, col0, row1, col1); // launch 1
    k_prep<<<dim3(PREP_BLOCKS, 2), 1024>>>(x0, x1);                          // launch 2
    k_gather<<<dim3((N_NODES * 32 + 255) / 256, 2), 256>>>();                // launch 3
    k_gemm_pool<<<dim3(TILES, 2), 512, SMEM_GEMM>>>(convW0, convB0, convW1, convB1, bat0, bat1); // launch 4 (captured)

    k_fcp<<<dim3(NB, 2), 128>>>(fcp1W, fcp1B, fcp2W, fcp2B);
    k_fc1<<<NB, 256>>>(fc1W, fc1B);
    k_fc2<<<NB, 64>>>(fc2W, fc2B);
    k_out<<<1, 128>>>(outW, outB, (float*)d_out);
}

// round 14
// speedup vs baseline: 1.4337x; 1.0431x over previous
#include <cuda_runtime.h>
#include <cuda_fp16.h>
#include <cstdint>
#include <math.h>
#include <float.h>

#define N_NODES 100000
#define N_EDGES 1600000
#define DIM 128
#define NB 128
#define NEG 0.01f
#define PREP_BLOCKS 98   // ceil(100000/1024)
#define TILES 782        // ceil(100000/128)
#define CAP 128          // bucket capacity per node (mean deg 16; P(>=128) ~ 0)

// ---------------- scratch (static device globals; no allocation) ----------------
__device__ int g_deg[2][N_NODES];            // zeroed by one cudaMemsetAsync per call
__device__ __align__(16) uint2 g_xh[2][(size_t)N_NODES * 32]; // pre-scaled x̂ fp16 (dinv[src]*x)
__device__ float  g_dinv[2][N_NODES];
__device__ int    g_buck[2][(size_t)N_NODES * CAP];           // padded CSR buckets (src per slot)
// A operand in mma-fragment layout: frag (tile, rb(8), kc(8)) = 256 halves, thread-contiguous
__device__ __align__(16) __half g_Ah[2][(size_t)TILES * 64 * 256];
__device__ float g_pool[2 * NB * DIM];
__device__ float g_gp[2 * NB * DIM];
__device__ float g_c1[NB * 256];
__device__ float g_c2[NB * 64];

__device__ __forceinline__ float lrelu(float v) { return v >= 0.f ? v : NEG * v; }

__device__ __forceinline__ void atomicMaxFloat(float* addr, float v) {
    if (v >= 0.f) atomicMax((int*)addr, __float_as_int(v));
    else          atomicMin((unsigned int*)addr, __float_as_uint(v));
}

// mma.sync m16n8k16 fp16 in / fp32 accum (sm_80 PTX; legal on compute_103)
#define MMA4(c, a, bb0, bb1) \
    asm volatile("mma.sync.aligned.m16n8k16.row.col.f32.f16.f16.f32 " \
        "{%0,%1,%2,%3}, {%4,%5,%6,%7}, {%8,%9}, {%0,%1,%2,%3};" \
        : "+f"((c)[0]), "+f"((c)[1]), "+f"((c)[2]), "+f"((c)[3]) \
        : "r"((a).x), "r"((a).y), "r"((a).z), "r"((a).w), "r"(bb0), "r"(bb1))

// ---------------- launch 1: bucket fill (count + scatter in one pass) ----------------
__global__ void k_fill(const int* __restrict__ row0, const int* __restrict__ col0,
                       const int* __restrict__ row1, const int* __restrict__ col1) {
    int p = blockIdx.y;
    const int* row = p ? row1 : row0;
    const int* col = p ? col1 : col0;
    int e = blockIdx.x * blockDim.x + threadIdx.x;
    if (e < N_EDGES) {
        int d = col[e];
        int pos = atomicAdd(&g_deg[p][d], 1);
        g_buck[p][(size_t)d * CAP + pos] = row[e];
    }
}

// ---------------- launch 2: dinv + pool init + x̂ transcode ----------------
__global__ void k_prep(const float* __restrict__ x0, const float* __restrict__ x1) {
    const int p = blockIdx.y;
    const int b = blockIdx.x;
    const int t = threadIdx.x;
    const int i = b * 1024 + t;
    const int lane = t & 31;

    if (i < N_NODES) g_dinv[p][i] = rsqrtf((float)(g_deg[p][i] + 1));   // +1 self loop
    if (b == 0) {
        #pragma unroll
        for (int it = 0; it < 16; it++)
            g_pool[p * NB * DIM + it * 1024 + t] = -FLT_MAX;
    }

    // transcode: x̂ = dinv[src] * x (fp16), coalesced, 32 nodes/warp
    {
        const float4* xs = (const float4*)(p ? x1 : x0);
        const int w = t >> 5;
        const int nb = b * 1024 + w * 32;
        for (int nd = 0; nd < 32; nd++) {
            int i2 = nb + nd;
            if (i2 >= N_NODES) break;
            float s = rsqrtf((float)(g_deg[p][i2] + 1));
            float4 xv = xs[(size_t)i2 * 32 + lane];
            __half2 h0 = __floats2half2_rn(s * xv.x, s * xv.y);
            __half2 h1 = __floats2half2_rn(s * xv.z, s * xv.w);
            uint2 o;
            o.x = *(unsigned*)&h0; o.y = *(unsigned*)&h1;
            g_xh[p][(size_t)i2 * 32 + lane] = o;
        }
    }
}

// ---------------- launch 3: gather (pre-scaled fp16) -> mma-frag fp16 A ----------------
__global__ void k_gather() {
    int p = blockIdx.y;
    const char* xb = (const char*)g_xh[p];       // byte base; row = 256B
    int gw = (blockIdx.x * blockDim.x + threadIdx.x) >> 5;
    int lane = threadIdx.x & 31;
    if (gw >= N_NODES) return;
    const int i = gw;
    const float di = g_dinv[p][i];
    const unsigned lb = (unsigned)lane * 8u;     // lane byte offset within row
    const int* csr = g_buck[p] + (size_t)i * CAP;

    float4 acc;
    {
        uint2 u = *(const uint2*)(xb + (unsigned)i * 256u + lb);   // self term
        float2 fa = __half22float2(*(__half2*)&u.x), fb = __half22float2(*(__half2*)&u.y);
        acc.x = fa.x; acc.y = fa.y; acc.z = fb.x; acc.w = fb.y;
    }

    int j = 0;
    const int s1 = g_deg[p][i];
    for (; j + 4 <= s1; j += 4) {
        unsigned oa = (unsigned)csr[j]     * 256u + lb;
        unsigned ob = (unsigned)csr[j + 1] * 256u + lb;
        unsigned oc = (unsigned)csr[j + 2] * 256u + lb;
        unsigned od = (unsigned)csr[j + 3] * 256u + lb;
        uint2 ua = *(const uint2*)(xb + oa);
        uint2 ub = *(const uint2*)(xb + ob);
        uint2 uc = *(const uint2*)(xb + oc);
        uint2 ud = *(const uint2*)(xb + od);
        float2 a0 = __half22float2(*(__half2*)&ua.x), a1 = __half22float2(*(__half2*)&ua.y);
        float2 b0 = __half22float2(*(__half2*)&ub.x), b1 = __half22float2(*(__half2*)&ub.y);
        float2 c0 = __half22float2(*(__half2*)&uc.x), c1 = __half22float2(*(__half2*)&uc.y);
        float2 d0 = __half22float2(*(__half2*)&ud.x), d1 = __half22float2(*(__half2*)&ud.y);
        acc.x += a0.x + b0.x + c0.x + d0.x;
        acc.y += a0.y + b0.y + c0.y + d0.y;
        acc.z += a1.x + b1.x + c1.x + d1.x;
        acc.w += a1.y + b1.y + c1.y + d1.y;
    }
    for (; j < s1; j++) {
        uint2 u = *(const uint2*)(xb + (unsigned)csr[j] * 256u + lb);
        float2 f0 = __half22float2(*(__half2*)&u.x), f1 = __half22float2(*(__half2*)&u.y);
        acc.x += f0.x; acc.y += f0.y; acc.z += f1.x; acc.w += f1.y;
    }
    acc.x *= di; acc.y *= di; acc.z *= di; acc.w *= di;

    __half2 hp0 = __floats2half2_rn(acc.x, acc.y);
    __half2 hp1 = __floats2half2_rn(acc.z, acc.w);

    // fragment-layout offsets: lane j handles k = j*4..j*4+3
    const int tile = i >> 7;
    const int rb = (i >> 4) & 7;          // 16-row frag within tile
    const int r16 = i & 15;
    const int kc = lane >> 2;             // k-chunk
    const int kl = (lane & 3) * 4;        // k within chunk (0,4,8,12)
    const int lane_f = ((r16 & 7) << 2) + ((kl & 7) >> 1);
    const int reg = ((r16 >> 3) & 1) + ((kl >> 3) << 1);
    const size_t base = ((((size_t)tile * 8 + rb) * 8 + kc) << 8) + (size_t)(lane_f * 8 + reg * 2);

    __half* Ah = g_Ah[p];
    *(__half2*)&Ah[base]     = hp0;       // (k, k+1)
    *(__half2*)&Ah[base + 8] = hp1;       // (k+2, k+3)
}

// ---------------- launch 4 (CAPTURED): mma.sync fp16 GEMM, frag-ordered W smem ----------------
// 512 threads: 16 warps = 8 M-frags x 2 N-halves. W in smem as uint2 frags:
// sW[nb(16)][kc(8)][lane(32)] = {b0h, b1h} -> one LDS.64 + one MMA per (jj,kc).
#define SMEM_GEMM (4096 * 8 + 512)

__global__ void __launch_bounds__(512, 2)
k_gemm_pool(const float* __restrict__ W0, const float* __restrict__ b0,
            const float* __restrict__ W1, const float* __restrict__ b1,
            const int* __restrict__ batch0, const int* __restrict__ batch1) {
    extern __shared__ uint2 sW[];                // 4096 uint2 = 32KB
    float* s_bias = (float*)(sW + 4096);

    const int p = blockIdx.y, tile = blockIdx.x;
    const float* __restrict__ W     = p ? W1 : W0;
    const float* __restrict__ bias  = p ? b1 : b0;
    const int*   __restrict__ batch = p ? batch1 : batch0;
    const int tid = threadIdx.x, lane = tid & 31, w = tid >> 5;
    const int w_m = w & 7, nh = w >> 3;

    // stage W -> fragment-ordered smem (one-time, 8 uint2/thread)
    #pragma unroll
    for (int it = 0; it < 8; it++) {
        int idx = tid + it * 512;                // 0..4095
        int lane_s = idx & 31;
        int kc_s = (idx >> 5) & 7;
        int nb_s = idx >> 8;                     // 0..15
        int n = nb_s * 8 + (lane_s >> 2);
        int k0 = (kc_s * 8 + (lane_s & 3)) * 2;  // pairs at k0,k0+1 and k0+8,k0+9
        float w00 = W[k0 * 128 + n];
        float w01 = W[(k0 + 1) * 128 + n];
        float w10 = W[(k0 + 8) * 128 + n];
        float w11 = W[(k0 + 9) * 128 + n];
        __half2 ph0 = __floats2half2_rn(w00, w01);
        __half2 ph1 = __floats2half2_rn(w10, w11);
        uint2 frag;
        frag.x = *(unsigned*)&ph0; frag.y = *(unsigned*)&ph1;
        sW[idx] = frag;
    }
    if (tid < 128) s_bias[tid] = bias[tid];
    __syncthreads();

    float acc[8][4];
    #pragma unroll
    for (int jj = 0; jj < 8; jj++)
        #pragma unroll
        for (int q = 0; q < 4; q++) acc[jj][q] = 0.f;

    const __half* Ah = g_Ah[p];
    const size_t abase = ((size_t)tile * 8 + w_m) * 8;
    #pragma unroll
    for (int kc = 0; kc < 8; kc++) {
        uint4 ah = *(const uint4*)&Ah[((abase + kc) << 8) + lane * 8];
        #pragma unroll
        for (int jj = 0; jj < 8; jj++) {
            uint2 bf = sW[(((nh * 8 + jj) * 8 + kc) << 5) + lane];   // one LDS.64
            MMA4(acc[jj], ah, bf.x, bf.y);
        }
    }

    // epilogue: segment_max into pool
    const int r_base = tile * 128 + w_m * 16;
    float* pool = &g_pool[p * NB * DIM];
    const bool full = (r_base + 15 < N_NODES);
    const bool any  = (r_base < N_NODES);
    int btA = any ? batch[r_base] : -1;
    int btB = full ? batch[r_base + 15] : -2;

    if (full && btA == btB) {
        #pragma unroll
        for (int jj = 0; jj < 8; jj++) {
            float m0 = fmaxf(acc[jj][0], acc[jj][2]);
            float m1 = fmaxf(acc[jj][1], acc[jj][3]);
            #pragma unroll
            for (int o = 4; o <= 16; o <<= 1) {
                m0 = fmaxf(m0, __shfl_xor_sync(0xffffffffu, m0, o));
                m1 = fmaxf(m1, __shfl_xor_sync(0xffffffffu, m1, o));
            }
            if ((lane >> 2) == 0) {
                int c = (nh * 8 + jj) * 8 + (lane & 3) * 2;
                atomicMaxFloat(&pool[btA * DIM + c],     lrelu(m0 + s_bias[c]));
                atomicMaxFloat(&pool[btA * DIM + c + 1], lrelu(m1 + s_bias[c + 1]));
            }
        }
    } else if (any) {
        int r0 = r_base + (lane >> 2), r1 = r0 + 8;
        int bt0 = (r0 < N_NODES) ? batch[r0] : -1;
        int bt1 = (r1 < N_NODES) ? batch[r1] : -1;
        #pragma unroll
        for (int jj = 0; jj < 8; jj++) {
            int c = (nh * 8 + jj) * 8 + (lane & 3) * 2;
            if (bt0 >= 0) {
                atomicMaxFloat(&pool[bt0 * DIM + c],     lrelu(acc[jj][0] + s_bias[c]));
                atomicMaxFloat(&pool[bt0 * DIM + c + 1], lrelu(acc[jj][1] + s_bias[c + 1]));
            }
            if (bt1 >= 0) {
                atomicMaxFloat(&pool[bt1 * DIM + c],     lrelu(acc[jj][2] + s_bias[c]));
                atomicMaxFloat(&pool[bt1 * DIM + c + 1], lrelu(acc[jj][3] + s_bias[c + 1]));
            }
        }
    }
}

// ---------------- tail MLPs (tiny) ----------------
__global__ void k_fcp(const float* __restrict__ W1, const float* __restrict__ b1,
                      const float* __restrict__ W2, const float* __restrict__ b2) {
    int p = blockIdx.y, r = blockIdx.x, d = threadIdx.x;
    __shared__ float prow[128];
    prow[d] = g_pool[p * NB * DIM + r * 128 + d];
    __syncthreads();
    const float* W = p ? W2 : W1;
    const float* bb = p ? b2 : b1;
    float s = bb[d];
    #pragma unroll 8
    for (int k = 0; k < 128; k++) s += prow[k] * W[k * 128 + d];
    g_gp[p * NB * DIM + r * 128 + d] = lrelu(s);
}

__global__ void k_fc1(const float* __restrict__ W, const float* __restrict__ b) {
    int r = blockIdx.x, d = threadIdx.x;
    __shared__ float in[256];
    in[d] = (d < 128) ? g_gp[r * 128 + d] : g_gp[NB * DIM + r * 128 + (d - 128)];
    __syncthreads();
    float s = b[d];
    #pragma unroll 8
    for (int k = 0; k < 256; k++) s += in[k] * W[k * 256 + d];
    g_c1[r * 256 + d] = lrelu(s);
}

__global__ void k_fc2(const float* __restrict__ W, const float* __restrict__ b) {
    int r = blockIdx.x, d = threadIdx.x;
    __shared__ float in[256];
    for (int k = d; k < 256; k += 64) in[k] = g_c1[r * 256 + k];
    __syncthreads();
    float s = b[d];
    #pragma unroll 8
    for (int k = 0; k < 256; k++) s += in[k] * W[k * 64 + d];
    g_c2[r * 64 + d] = lrelu(s);
}

__global__ void k_out(const float* __restrict__ W, const float* __restrict__ b,
                      float* __restrict__ out) {
    int r = threadIdx.x;
    float s = b[0];
    #pragma unroll
    for (int k = 0; k < 64; k++) s += g_c2[r * 64 + k] * W[k];
    out[r] = 1.f / (1.f + expf(-s));
}

// ---------------- host launcher ----------------
extern "C" void kernel_launch(void* const* d_in, const int* in_sizes, int n_in,
                              void* d_out, int out_size) {
    int ix[2], ie[2], ib[2];
    if (in_sizes[1] == N_NODES * DIM) {
        ix[0] = 0; ix[1] = 1; ie[0] = 2; ie[1] = 3; ib[0] = 4; ib[1] = 5;   // dict order
    } else {
        ix[0] = 0; ie[0] = 1; ib[0] = 2; ix[1] = 3; ie[1] = 4; ib[1] = 5;   // signature order
    }
    const float* x0 = (const float*)d_in[ix[0]];
    const float* x1 = (const float*)d_in[ix[1]];
    const int* row0 = (const int*)d_in[ie[0]];
    const int* col0 = row0 + N_EDGES;
    const int* row1 = (const int*)d_in[ie[1]];
    const int* col1 = row1 + N_EDGES;
    const int* bat0 = (const int*)d_in[ib[0]];
    const int* bat1 = (const int*)d_in[ib[1]];

    const float* convW0 = (const float*)d_in[6];
    const float* convB0 = (const float*)d_in[7];
    const float* convW1 = (const float*)d_in[8];
    const float* convB1 = (const float*)d_in[9];
    const float* fcp1W = (const float*)d_in[10];
    const float* fcp1B = (const float*)d_in[11];
    const float* fcp2W = (const float*)d_in[12];
    const float* fcp2B = (const float*)d_in[13];
    const float* fc1W  = (const float*)d_in[14];
    const float* fc1B  = (const float*)d_in[15];
    const float* fc2W  = (const float*)d_in[16];
    const float* fc2B  = (const float*)d_in[17];
    const float* outW  = (const float*)d_in[18];
    const float* outB  = (const float*)d_in[19];

    static bool attr_done = false;
    if (!attr_done) {
        cudaFuncSetAttribute(k_gemm_pool, cudaFuncAttributeMaxDynamicSharedMemorySize, SMEM_GEMM);
        attr_done = true;
    }

    void* degPtr = nullptr;
    cudaGetSymbolAddress(&degPtr, g_deg);
    cudaMemsetAsync(degPtr, 0, 2 * N_NODES * sizeof(int));

    k_fill<<<dim3((N_EDGES + 255) / 256, 2), 256>>>(row0, col0, row1, col1); // launch 1
    k_prep<<<dim3(PREP_BLOCKS, 2), 1024>>>(x0, x1);                          // launch 2
    k_gather<<<dim3((N_NODES * 32 + 255) / 256, 2), 256>>>();                // launch 3
    k_gemm_pool<<<dim3(TILES, 2), 512, SMEM_GEMM>>>(convW0, convB0, convW1, convB1, bat0, bat1); // launch 4 (captured)

    k_fcp<<<dim3(NB, 2), 128>>>(fcp1W, fcp1B, fcp2W, fcp2B);
    k_fc1<<<NB, 256>>>(fc1W, fc1B);
    k_fc2<<<NB, 64>>>(fc2W, fc2B);
    k_out<<<1, 128>>>(outW, outB, (float*)d_out);
}